// round 14
// baseline (speedup 1.0000x reference)
#include <cuda_runtime.h>
#include <cuda_fp16.h>
#include <math.h>
#include <stdint.h>

#define NN 50000
#define EE 512000
#define E2 (EE/2)
#define DINF 128
#define HC 128
#define CC 32
#define HH 4
#define AYW 656   // 128 va | 512 y | 1 ind | 15 pad
#define QS 384
#define NB_SCAN ((NN + 1023) / 1024)

// ---------------- scratch ----------------
__device__ float    g_qf[(size_t)NN*HC];       // q fp32
__device__ __half   g_kv[(size_t)NN*256];      // [k | v] fp16
__device__ float    g_wqkv[DINF*QS];
__device__ float    g_bqkv[QS];
__device__ float    g_u[(size_t)NN*HH*DINF];
__device__ float    g_we2t[DINF*HC];
__device__ float    g_ay[(size_t)NN*AYW];
__device__ float    g_axh[(size_t)NN*256];
__device__ float    g_wbig[AYW*CC];
__device__ float    g_wh[256*CC];
__device__ float    g_xgat[NN*CC];
__device__ float    g_o1[NN*CC];
__device__ double   g_sum[CC];
__device__ double   g_sumsq[CC];
__device__ float    g_mu[CC];
__device__ float    g_rstd[CC];
// CSR
__device__ int      g_cntA[NN];
__device__ int      g_cntH[NN];
__device__ int      g_offA[NN+1];
__device__ int      g_offH[NN+1];
__device__ int      g_curA[NN];
__device__ int      g_curH[NN];
__device__ int      g_payA[EE];
__device__ int      g_payH[EE];
__device__ int      g_blkA[NB_SCAN+1];
__device__ int      g_blkH[NB_SCAN+1];

// ---------------- f32x2 helpers ----------------
__device__ __forceinline__ unsigned long long pack2(float lo, float hi) {
    unsigned long long r;
    asm("mov.b64 %0, {%1, %2};" : "=l"(r) : "f"(lo), "f"(hi));
    return r;
}
__device__ __forceinline__ void fma2(unsigned long long& d, unsigned long long a, unsigned long long b) {
    asm("fma.rn.f32x2 %0, %1, %2, %0;" : "+l"(d) : "l"(a), "l"(b));
}
__device__ __forceinline__ float2 unpack2(unsigned long long v) {
    float lo, hi;
    asm("mov.b64 {%0, %1}, %2;" : "=f"(lo), "=f"(hi) : "l"(v));
    return make_float2(lo, hi);
}

// ---------------- setup ----------------
__global__ void setup_kernel(const float* __restrict__ We2,
                             const float* __restrict__ Wcon, const float* __restrict__ We3,
                             const float* __restrict__ be3,
                             const float* __restrict__ Wh1, const float* __restrict__ Wh2,
                             const float* __restrict__ Wq, const float* __restrict__ bq,
                             const float* __restrict__ Wk, const float* __restrict__ bk,
                             const float* __restrict__ Wv, const float* __restrict__ bv) {
    int tid = blockIdx.x * blockDim.x + threadIdx.x;
    int stride = gridDim.x * blockDim.x;
    for (int j = tid; j < NN; j += stride) { g_cntA[j]=0; g_cntH[j]=0; }
    if (tid < CC) { g_sum[tid]=0.0; g_sumsq[tid]=0.0; }
    for (int i = tid; i < DINF*HC; i += stride) {
        int f = i >> 7, o = i & 127;
        g_we2t[o*DINF + f] = We2[i];
    }
    for (int idx = tid; idx < AYW*CC; idx += stride) {
        int r = idx / CC, c = idx % CC;
        float v;
        if (r < 128) {
            v = Wcon[r*CC + c];
        } else if (r < 640) {
            int h = (r - 128) >> 7, f = (r - 128) & 127;
            float a = 0.f;
            #pragma unroll
            for (int c2 = 0; c2 < 32; c2++)
                a = fmaf(We3[f*HC + h*32 + c2], Wcon[(h*32 + c2)*CC + c], a);
            v = a;
        } else if (r == 640) {
            float a = 0.f;
            for (int k = 0; k < HC; k++)
                a = fmaf(be3[k], Wcon[k*CC + c], a);
            v = a;
        } else v = 0.f;
        g_wbig[r*CC + c] = v;
    }
    for (int j = tid; j < 256*CC; j += stride) {
        int r = j / CC, c = j % CC;
        g_wh[r*CC + c] = (r < 128) ? Wh1[r*CC + c] : Wh2[(r-128)*CC + c];
    }
    for (int j = tid; j < DINF*QS; j += stride) {
        int f = j / QS, n = j % QS;
        float v = (n < 128) ? Wq[f*HC + n] : (n < 256) ? Wk[f*HC + n - 128] : Wv[f*HC + n - 256];
        g_wqkv[j] = v;
    }
    if (tid < QS) {
        g_bqkv[tid] = (tid < 128) ? bq[tid] : (tid < 256) ? bk[tid-128] : bv[tid-256];
    }
}

// ---------------- CSR build ----------------
__global__ void csr_count(const int* __restrict__ ei) {
    int i = blockIdx.x * blockDim.x + threadIdx.x;
    if (i >= EE) return;
    atomicAdd(&g_cntA[ei[EE + i]], 1);
    if (i < E2) {
        atomicAdd(&g_cntH[ei[i]],      1);
        atomicAdd(&g_cntH[ei[EE + i]], 1);
    }
}

__global__ void scan1(const int* __restrict__ cnt, int* __restrict__ off, int* __restrict__ blk) {
    __shared__ int sd[1024];
    int tid = threadIdx.x;
    int i = blockIdx.x * 1024 + tid;
    int v = (i < NN) ? cnt[i] : 0;
    sd[tid] = v;
    __syncthreads();
    #pragma unroll
    for (int ofs = 1; ofs < 1024; ofs <<= 1) {
        int t = (tid >= ofs) ? sd[tid - ofs] : 0;
        __syncthreads();
        sd[tid] += t;
        __syncthreads();
    }
    if (i < NN) off[i] = sd[tid] - v;
    if (tid == 1023) blk[blockIdx.x] = sd[1023];
}

__global__ void scan2(int* __restrict__ blk) {
    if (threadIdx.x == 0) {
        int run = 0;
        for (int b = 0; b < NB_SCAN; b++) { int t = blk[b]; blk[b] = run; run += t; }
        blk[NB_SCAN] = run;
    }
}

__global__ void scan3(int* __restrict__ off, int* __restrict__ cur, const int* __restrict__ blk) {
    int i = blockIdx.x * blockDim.x + threadIdx.x;
    if (i < NN) {
        int o = off[i] + blk[i >> 10];
        off[i] = o;
        cur[i] = o;
    }
    if (i == 0) off[NN] = blk[NB_SCAN];
}

__global__ void csr_fill(const int* __restrict__ ei) {
    int i = blockIdx.x * blockDim.x + threadIdx.x;
    if (i >= EE) return;
    int d = ei[EE + i];
    int pos = atomicAdd(&g_curA[d], 1);
    g_payA[pos] = i;
    if (i < E2) {
        int p1 = atomicAdd(&g_curH[ei[i]], 1);
        g_payH[p1] = i;
        int p2 = atomicAdd(&g_curH[ei[EE + i]], 1);
        g_payH[p2] = i;
    }
}

// ---------------- SGEMM: pre-splatted W smem, row-pair f32x2 accum, zero packs in loop ----------------
template<int BM, int BN, int BK, int TM, int TN, bool QKV = false>
__global__ void __launch_bounds__((BM/TM)*(BN/TN), 2)
gemm_bias(const float* __restrict__ A, const float* __restrict__ W,
          const float* __restrict__ bias, float* __restrict__ C,
          int M, int N, int K) {
    constexpr int THREADS = (BM/TM)*(BN/TN);
    constexpr int A4 = BM*BK/4;
    constexpr int W4 = BK*BN/4;
    constexpr int AI = (A4 + THREADS - 1)/THREADS;
    constexpr int WI = (W4 + THREADS - 1)/THREADS;
    __shared__ float As[2][BK][BM+4];
    __shared__ unsigned long long Wsd[2][BK][BN];   // pre-splatted (w,w)
    const int tid  = threadIdx.x;
    const int brow = blockIdx.y * BM;
    const int bcol = blockIdx.x * BN;
    const int trow = (tid / (BN/TN)) * TM;
    const int tcol = (tid % (BN/TN)) * TN;

    float4 stA[AI];
    float4 stW[WI];

    auto loadg = [&](int k0) {
        #pragma unroll
        for (int it = 0; it < AI; it++) {
            int i = tid + it*THREADS;
            if (i < A4) {
                int m = i / (BK/4), k4 = i % (BK/4);
                int gm = brow + m;
                stA[it] = (gm < M) ? *(const float4*)(A + (size_t)gm*K + k0 + k4*4)
                                   : make_float4(0.f,0.f,0.f,0.f);
            }
        }
        #pragma unroll
        for (int it = 0; it < WI; it++) {
            int i = tid + it*THREADS;
            if (i < W4) {
                int kk = i / (BN/4), n4 = i % (BN/4);
                stW[it] = *(const float4*)(W + (size_t)(k0+kk)*N + bcol + n4*4);
            }
        }
    };
    auto store_s = [&](int buf) {
        #pragma unroll
        for (int it = 0; it < AI; it++) {
            int i = tid + it*THREADS;
            if (i < A4) {
                int m = i / (BK/4), k4 = i % (BK/4);
                As[buf][k4*4+0][m] = stA[it].x;
                As[buf][k4*4+1][m] = stA[it].y;
                As[buf][k4*4+2][m] = stA[it].z;
                As[buf][k4*4+3][m] = stA[it].w;
            }
        }
        #pragma unroll
        for (int it = 0; it < WI; it++) {
            int i = tid + it*THREADS;
            if (i < W4) {
                int kk = i / (BN/4), n4 = i % (BN/4);
                Wsd[buf][kk][n4*4+0] = pack2(stW[it].x, stW[it].x);
                Wsd[buf][kk][n4*4+1] = pack2(stW[it].y, stW[it].y);
                Wsd[buf][kk][n4*4+2] = pack2(stW[it].z, stW[it].z);
                Wsd[buf][kk][n4*4+3] = pack2(stW[it].w, stW[it].w);
            }
        }
    };

    // acc2[p][j]: rows (trow+2p, trow+2p+1) packed, column tcol+j
    unsigned long long acc2[TM/2][TN];
    #pragma unroll
    for (int p = 0; p < TM/2; p++)
        #pragma unroll
        for (int j = 0; j < TN; j++) acc2[p][j] = 0ULL;

    const int nt = K / BK;
    loadg(0);
    store_s(0);
    __syncthreads();

    for (int t = 0; t < nt; t++) {
        int cur = t & 1;
        if (t + 1 < nt) loadg((t+1)*BK);
        #pragma unroll
        for (int kk = 0; kk < BK; kk++) {
            unsigned long long raP[TM/2];
            #pragma unroll
            for (int i = 0; i < TM; i += 4) {
                ulonglong2 rp = *(const ulonglong2*)&As[cur][kk][trow + i];
                raP[i/2]   = rp.x;
                raP[i/2+1] = rp.y;
            }
            unsigned long long rbs[TN];
            #pragma unroll
            for (int j = 0; j < TN; j += 2) {
                ulonglong2 wv = *(const ulonglong2*)&Wsd[cur][kk][tcol + j];
                rbs[j] = wv.x; rbs[j+1] = wv.y;
            }
            #pragma unroll
            for (int p = 0; p < TM/2; p++)
                #pragma unroll
                for (int j = 0; j < TN; j++)
                    fma2(acc2[p][j], raP[p], rbs[j]);
        }
        if (t + 1 < nt) {
            store_s((t+1) & 1);
            __syncthreads();
        }
    }

    #pragma unroll
    for (int p = 0; p < TM/2; p++) {
        #pragma unroll
        for (int h = 0; h < 2; h++) {
            int gm = brow + trow + 2*p + h;
            if (gm >= M) continue;
            #pragma unroll
            for (int j = 0; j < TN; j += 4) {
                int gn = bcol + tcol + j;
                float2 t0 = unpack2(acc2[p][j+0]);
                float2 t1 = unpack2(acc2[p][j+1]);
                float2 t2 = unpack2(acc2[p][j+2]);
                float2 t3 = unpack2(acc2[p][j+3]);
                float4 v;
                v.x = (h ? t0.y : t0.x) + (bias ? bias[gn+0] : 0.f);
                v.y = (h ? t1.y : t1.x) + (bias ? bias[gn+1] : 0.f);
                v.z = (h ? t2.y : t2.x) + (bias ? bias[gn+2] : 0.f);
                v.w = (h ? t3.y : t3.x) + (bias ? bias[gn+3] : 0.f);
                if constexpr (QKV) {
                    if (bcol == 0) {
                        *(float4*)(g_qf + (size_t)gm*HC + gn) = v;
                    } else {
                        __half hh[4];
                        hh[0] = __float2half_rn(v.x); hh[1] = __float2half_rn(v.y);
                        hh[2] = __float2half_rn(v.z); hh[3] = __float2half_rn(v.w);
                        *(uint2*)(g_kv + (size_t)gm*256 + (gn - 128)) = *(uint2*)hh;
                    }
                } else {
                    *(float4*)(C + (size_t)gm*N + gn) = v;
                }
            }
        }
    }
}

// ---------------- dual small GEMM (N=32), same pre-splat scheme ----------------
__device__ __forceinline__ void gemm_body32(const float* __restrict__ A, const float* __restrict__ W,
                                            float* __restrict__ C, int K, int browblk) {
    __shared__ float As[2][16][132];
    __shared__ unsigned long long Wsd[2][16][32];
    const int tid  = threadIdx.x;
    const int brow = browblk * 128;
    const int trow = (tid / 8) * 4;
    const int tcol = (tid % 8) * 4;

    float4 stA[2];
    float4 stW;

    auto loadg = [&](int k0) {
        #pragma unroll
        for (int it = 0; it < 2; it++) {
            int i = tid + it*256;
            int m = i / 4, k4 = i % 4;
            int gm = brow + m;
            stA[it] = (gm < NN) ? *(const float4*)(A + (size_t)gm*K + k0 + k4*4)
                                : make_float4(0.f,0.f,0.f,0.f);
        }
        if (tid < 128) {
            int kk = tid / 8, n4 = tid % 8;
            stW = *(const float4*)(W + (size_t)(k0+kk)*32 + n4*4);
        }
    };
    auto store_s = [&](int buf) {
        #pragma unroll
        for (int it = 0; it < 2; it++) {
            int i = tid + it*256;
            int m = i / 4, k4 = i % 4;
            As[buf][k4*4+0][m] = stA[it].x;
            As[buf][k4*4+1][m] = stA[it].y;
            As[buf][k4*4+2][m] = stA[it].z;
            As[buf][k4*4+3][m] = stA[it].w;
        }
        if (tid < 128) {
            int kk = tid / 8, n4 = tid % 8;
            Wsd[buf][kk][n4*4+0] = pack2(stW.x, stW.x);
            Wsd[buf][kk][n4*4+1] = pack2(stW.y, stW.y);
            Wsd[buf][kk][n4*4+2] = pack2(stW.z, stW.z);
            Wsd[buf][kk][n4*4+3] = pack2(stW.w, stW.w);
        }
    };

    unsigned long long acc2[2][4];
    #pragma unroll
    for (int p = 0; p < 2; p++)
        #pragma unroll
        for (int j = 0; j < 4; j++) acc2[p][j] = 0ULL;

    const int nt = K / 16;
    loadg(0);
    store_s(0);
    __syncthreads();

    for (int t = 0; t < nt; t++) {
        int cur = t & 1;
        if (t + 1 < nt) loadg((t+1)*16);
        #pragma unroll
        for (int kk = 0; kk < 16; kk++) {
            ulonglong2 rp = *(const ulonglong2*)&As[cur][kk][trow];
            ulonglong2 w0 = *(const ulonglong2*)&Wsd[cur][kk][tcol];
            ulonglong2 w1 = *(const ulonglong2*)&Wsd[cur][kk][tcol + 2];
            fma2(acc2[0][0], rp.x, w0.x); fma2(acc2[0][1], rp.x, w0.y);
            fma2(acc2[0][2], rp.x, w1.x); fma2(acc2[0][3], rp.x, w1.y);
            fma2(acc2[1][0], rp.y, w0.x); fma2(acc2[1][1], rp.y, w0.y);
            fma2(acc2[1][2], rp.y, w1.x); fma2(acc2[1][3], rp.y, w1.y);
        }
        if (t + 1 < nt) {
            store_s((t+1) & 1);
            __syncthreads();
        }
    }

    #pragma unroll
    for (int p = 0; p < 2; p++) {
        #pragma unroll
        for (int h = 0; h < 2; h++) {
            int gm = brow + trow + 2*p + h;
            if (gm >= NN) continue;
            float2 t0 = unpack2(acc2[p][0]);
            float2 t1 = unpack2(acc2[p][1]);
            float2 t2 = unpack2(acc2[p][2]);
            float2 t3 = unpack2(acc2[p][3]);
            float4 v;
            v.x = h ? t0.y : t0.x;
            v.y = h ? t1.y : t1.x;
            v.z = h ? t2.y : t2.x;
            v.w = h ? t3.y : t3.x;
            *(float4*)(C + (size_t)gm*32 + tcol) = v;
        }
    }
}

#define NB32 ((NN + 127) / 128)
__global__ void __launch_bounds__(256, 2) gemm_dual() {
    bool second = blockIdx.y >= NB32;
    const float* A = second ? g_axh : g_ay;
    const float* W = second ? g_wh  : g_wbig;
    float*       C = second ? g_o1  : g_xgat;
    int          K = second ? 256   : AYW;
    int        blk = second ? (blockIdx.y - NB32) : blockIdx.y;
    gemm_body32(A, W, C, K, blk);
}

// ---------------- u precompute ----------------
#define GN 32
__global__ void compute_u() {
    extern __shared__ float shm[];
    float (*sW)[132] = (float (*)[132])shm;
    float (*sq)[128] = (float (*)[128])(shm + 128*132);
    int tid = threadIdx.x;
    int n0 = blockIdx.x * GN;
    for (int i = tid; i < 128*128; i += 256) {
        int o = i >> 7, f = i & 127;
        sW[o][f] = g_we2t[i];
    }
    for (int i = tid; i < GN*128; i += 256) {
        int nl = i >> 7, c = i & 127;
        int n = n0 + nl;
        sq[nl][c] = (n < NN) ? g_qf[(size_t)n*HC + c] : 0.f;
    }
    __syncthreads();
    int w = tid >> 5, lane = tid & 31;
    for (int p = w; p < GN*HH; p += 8) {
        int nl = p >> 2, h = p & 3;
        int n = n0 + nl;
        if (n >= NN) continue;
        float a0=0.f, a1=0.f, a2=0.f, a3=0.f;
        #pragma unroll
        for (int c = 0; c < 32; c++) {
            float qv = sq[nl][h*32 + c];
            const float* row = sW[h*32 + c];
            a0 = fmaf(qv, row[lane],      a0);
            a1 = fmaf(qv, row[lane + 32], a1);
            a2 = fmaf(qv, row[lane + 64], a2);
            a3 = fmaf(qv, row[lane + 96], a3);
        }
        size_t base = (size_t)n*512 + h*128;
        g_u[base + lane]      = a0;
        g_u[base + lane + 32] = a1;
        g_u[base + lane + 64] = a2;
        g_u[base + lane + 96] = a3;
    }
}

// ---------------- fused edge kernel: u in smem, occ 3, fp16 kv gathers ----------------
__global__ void __launch_bounds__(256, 3)
edge_fused(const int* __restrict__ ei, const float* __restrict__ ea,
           const float* __restrict__ be2, const float* __restrict__ x) {
    const unsigned FULL = 0xffffffffu;
    __shared__ float su[8][4][132];
    const int lane = threadIdx.x & 31;
    const int w = threadIdx.x >> 5;
    const int node = (blockIdx.x >> 1) * 8 + w;
    if (node >= NN) return;

    if ((blockIdx.x & 1) == 0) {
        // ---- attention: warp per dst node, 2-edge unrolled, fp16 kv ----
        const int g = lane >> 3, sub = lane & 7;
        const int d = node;
        const int beg = g_offA[d], end = g_offA[d+1];
        const float scale = 0.17677669529663687f;

        float4 qv = *(const float4*)&g_qf[(size_t)d*HC + g*32 + sub*4];
        float4 b2 = *(const float4*)&be2[g*32 + sub*4];
        float qb2 = qv.x*b2.x + qv.y*b2.y + qv.z*b2.z + qv.w*b2.w;
        #pragma unroll
        for (int j = 0; j < 4; j++) {
            float4 t = *(const float4*)&g_u[(size_t)d*512 + g*128 + sub*16 + j*4];
            *(float4*)&su[w][j][lane*4] = t;
        }
        __syncwarp();

        unsigned long long vaP0 = 0ULL, vaP1 = 0ULL;
        unsigned long long y0P0 = 0ULL, y0P1 = 0ULL;
        unsigned long long y1P0 = 0ULL, y1P1 = 0ULL;
        unsigned long long y2P0 = 0ULL, y2P1 = 0ULL;
        unsigned long long y3P0 = 0ULL, y3P1 = 0ULL;
        float s1 = 0.f, s20 = 0.f, s21 = 0.f, s22 = 0.f, s23 = 0.f;

        for (int base = beg; base < end; base += 32) {
            int m = end - base; if (m > 32) m = 32;
            int eL = 0, sL = 0;
            if (base + lane < end) {
                eL = g_payA[base + lane];
                sL = ei[eL];
            }
            int it = 0;
            for (; it + 1 < m; it += 2) {
                int e0 = __shfl_sync(FULL, eL, it),   s0  = __shfl_sync(FULL, sL, it);
                int e1 = __shfl_sync(FULL, eL, it+1), s1i = __shfl_sync(FULL, sL, it+1);
                const float* eb0 = ea + (size_t)e0*128;
                const float* eb1 = ea + (size_t)e1*128;
                const __half* kv0 = g_kv + (size_t)s0*256;
                const __half* kv1 = g_kv + (size_t)s1i*256;

                uint2 kr0 = *(const uint2*)(kv0 + g*32 + sub*4);
                uint2 kr1 = *(const uint2*)(kv1 + g*32 + sub*4);
                float2 t;
                t = __half22float2(*(__half2*)&kr0.x);
                float p1a = qv.x*t.x + qv.y*t.y;
                t = __half22float2(*(__half2*)&kr0.y);
                p1a += qv.z*t.x + qv.w*t.y;
                t = __half22float2(*(__half2*)&kr1.x);
                float p1b = qv.x*t.x + qv.y*t.y;
                t = __half22float2(*(__half2*)&kr1.y);
                p1b += qv.z*t.x + qv.w*t.y;
                float p2a = qb2, p2b = qb2;
                #pragma unroll
                for (int j = 0; j < 4; j++) {
                    float4 uj = *(const float4*)&su[w][j][lane*4];
                    float4 ev0 = *(const float4*)&eb0[sub*16 + j*4];
                    float4 ev1 = *(const float4*)&eb1[sub*16 + j*4];
                    p2a += ev0.x*uj.x + ev0.y*uj.y + ev0.z*uj.z + ev0.w*uj.w;
                    p2b += ev1.x*uj.x + ev1.y*uj.y + ev1.z*uj.z + ev1.w*uj.w;
                }
                #pragma unroll
                for (int o = 1; o < 8; o <<= 1) {
                    p1a += __shfl_xor_sync(FULL, p1a, o);
                    p2a += __shfl_xor_sync(FULL, p2a, o);
                    p1b += __shfl_xor_sync(FULL, p1b, o);
                    p2b += __shfl_xor_sync(FULL, p2b, o);
                }
                float ex1a = __expf(p1a * scale), ex2a = __expf(p2a * scale);
                float ex1b = __expf(p1b * scale), ex2b = __expf(p2b * scale);
                s1 += ex1a + ex1b;
                float e20a = __shfl_sync(FULL, ex2a, 0),  e20b = __shfl_sync(FULL, ex2b, 0);
                float e21a = __shfl_sync(FULL, ex2a, 8),  e21b = __shfl_sync(FULL, ex2b, 8);
                float e22a = __shfl_sync(FULL, ex2a, 16), e22b = __shfl_sync(FULL, ex2b, 16);
                float e23a = __shfl_sync(FULL, ex2a, 24), e23b = __shfl_sync(FULL, ex2b, 24);
                s20 += e20a + e20b; s21 += e21a + e21b;
                s22 += e22a + e22b; s23 += e23a + e23b;

                float4 ey0 = *(const float4*)&eb0[lane*4];
                float4 ey1 = *(const float4*)&eb1[lane*4];
                uint2 vr0 = *(const uint2*)(kv0 + 128 + lane*4);
                uint2 vr1 = *(const uint2*)(kv1 + 128 + lane*4);
                unsigned long long ey0lo = pack2(ey0.x, ey0.y), ey0hi = pack2(ey0.z, ey0.w);
                unsigned long long ey1lo = pack2(ey1.x, ey1.y), ey1hi = pack2(ey1.z, ey1.w);
                unsigned long long x1a = pack2(ex1a, ex1a), x1b = pack2(ex1b, ex1b);
                t = __half22float2(*(__half2*)&vr0.x);
                fma2(vaP0, x1a, pack2(t.x, t.y));
                t = __half22float2(*(__half2*)&vr0.y);
                fma2(vaP1, x1a, pack2(t.x, t.y));
                t = __half22float2(*(__half2*)&vr1.x);
                fma2(vaP0, x1b, pack2(t.x, t.y));
                t = __half22float2(*(__half2*)&vr1.y);
                fma2(vaP1, x1b, pack2(t.x, t.y));
                unsigned long long c0a = pack2(e20a, e20a), c0b = pack2(e20b, e20b);
                fma2(y0P0, c0a, ey0lo); fma2(y0P0, c0b, ey1lo);
                fma2(y0P1, c0a, ey0hi); fma2(y0P1, c0b, ey1hi);
                unsigned long long c1a = pack2(e21a, e21a), c1b = pack2(e21b, e21b);
                fma2(y1P0, c1a, ey0lo); fma2(y1P0, c1b, ey1lo);
                fma2(y1P1, c1a, ey0hi); fma2(y1P1, c1b, ey1hi);
                unsigned long long c2a = pack2(e22a, e22a), c2b = pack2(e22b, e22b);
                fma2(y2P0, c2a, ey0lo); fma2(y2P0, c2b, ey1lo);
                fma2(y2P1, c2a, ey0hi); fma2(y2P1, c2b, ey1hi);
                unsigned long long c3a = pack2(e23a, e23a), c3b = pack2(e23b, e23b);
                fma2(y3P0, c3a, ey0lo); fma2(y3P0, c3b, ey1lo);
                fma2(y3P1, c3a, ey0hi); fma2(y3P1, c3b, ey1hi);
            }
            if (it < m) {
                int e0 = __shfl_sync(FULL, eL, it), s0 = __shfl_sync(FULL, sL, it);
                const float* eb0 = ea + (size_t)e0*128;
                const __half* kv0 = g_kv + (size_t)s0*256;
                uint2 kr0 = *(const uint2*)(kv0 + g*32 + sub*4);
                float2 t;
                t = __half22float2(*(__half2*)&kr0.x);
                float p1a = qv.x*t.x + qv.y*t.y;
                t = __half22float2(*(__half2*)&kr0.y);
                p1a += qv.z*t.x + qv.w*t.y;
                float p2a = qb2;
                #pragma unroll
                for (int j = 0; j < 4; j++) {
                    float4 uj = *(const float4*)&su[w][j][lane*4];
                    float4 ev0 = *(const float4*)&eb0[sub*16 + j*4];
                    p2a += ev0.x*uj.x + ev0.y*uj.y + ev0.z*uj.z + ev0.w*uj.w;
                }
                #pragma unroll
                for (int o = 1; o < 8; o <<= 1) {
                    p1a += __shfl_xor_sync(FULL, p1a, o);
                    p2a += __shfl_xor_sync(FULL, p2a, o);
                }
                float ex1a = __expf(p1a * scale), ex2a = __expf(p2a * scale);
                s1 += ex1a;
                float e20a = __shfl_sync(FULL, ex2a, 0);
                float e21a = __shfl_sync(FULL, ex2a, 8);
                float e22a = __shfl_sync(FULL, ex2a, 16);
                float e23a = __shfl_sync(FULL, ex2a, 24);
                s20 += e20a; s21 += e21a; s22 += e22a; s23 += e23a;
                float4 ey0 = *(const float4*)&eb0[lane*4];
                uint2 vr0 = *(const uint2*)(kv0 + 128 + lane*4);
                unsigned long long ey0lo = pack2(ey0.x, ey0.y), ey0hi = pack2(ey0.z, ey0.w);
                unsigned long long x1a = pack2(ex1a, ex1a);
                t = __half22float2(*(__half2*)&vr0.x);
                fma2(vaP0, x1a, pack2(t.x, t.y));
                t = __half22float2(*(__half2*)&vr0.y);
                fma2(vaP1, x1a, pack2(t.x, t.y));
                unsigned long long c0a = pack2(e20a, e20a);
                fma2(y0P0, c0a, ey0lo); fma2(y0P1, c0a, ey0hi);
                unsigned long long c1a = pack2(e21a, e21a);
                fma2(y1P0, c1a, ey0lo); fma2(y1P1, c1a, ey0hi);
                unsigned long long c2a = pack2(e22a, e22a);
                fma2(y2P0, c2a, ey0lo); fma2(y2P1, c2a, ey0hi);
                unsigned long long c3a = pack2(e23a, e23a);
                fma2(y3P0, c3a, ey0lo); fma2(y3P1, c3a, ey0hi);
            }
        }

        float r1 = 1.f / (s1 + 1e-16f);
        float q0 = 1.f/(s20+1e-16f), q1 = 1.f/(s21+1e-16f);
        float q2 = 1.f/(s22+1e-16f), q3 = 1.f/(s23+1e-16f);
        float2 a, b;
        float* row = g_ay + (size_t)d*AYW;
        a = unpack2(vaP0); b = unpack2(vaP1);
        *(float4*)&row[lane*4] = make_float4(a.x*r1, a.y*r1, b.x*r1, b.y*r1);
        a = unpack2(y0P0); b = unpack2(y0P1);
        *(float4*)&row[128 + 0*128 + lane*4] = make_float4(a.x*q0, a.y*q0, b.x*q0, b.y*q0);
        a = unpack2(y1P0); b = unpack2(y1P1);
        *(float4*)&row[128 + 1*128 + lane*4] = make_float4(a.x*q1, a.y*q1, b.x*q1, b.y*q1);
        a = unpack2(y2P0); b = unpack2(y2P1);
        *(float4*)&row[128 + 2*128 + lane*4] = make_float4(a.x*q2, a.y*q2, b.x*q2, b.y*q2);
        a = unpack2(y3P0); b = unpack2(y3P1);
        *(float4*)&row[128 + 3*128 + lane*4] = make_float4(a.x*q3, a.y*q3, b.x*q3, b.y*q3);
        if (lane == 0)      row[640] = (end > beg) ? 1.f : 0.f;
        else if (lane < 16) row[640 + lane] = 0.f;
    } else {
        // ---- hyper aggregation: warp per node, 2-edge unrolled ----
        const int n = node;
        const int beg = g_offH[n], end = g_offH[n+1];
        float4 acc = make_float4(0.f,0.f,0.f,0.f);
        for (int base = beg; base < end; base += 32) {
            int m = end - base; if (m > 32) m = 32;
            int iL = 0;
            if (base + lane < end) iL = g_payH[base + lane];
            int it = 0;
            for (; it + 1 < m; it += 2) {
                int i0 = __shfl_sync(FULL, iL, it);
                int i1 = __shfl_sync(FULL, iL, it+1);
                float4 e0 = *(const float4*)&ea[(size_t)i0*128 + lane*4];
                float4 e1 = *(const float4*)&ea[(size_t)i1*128 + lane*4];
                acc.x += e0.x + e1.x; acc.y += e0.y + e1.y;
                acc.z += e0.z + e1.z; acc.w += e0.w + e1.w;
            }
            if (it < m) {
                int i0 = __shfl_sync(FULL, iL, it);
                float4 e0 = *(const float4*)&ea[(size_t)i0*128 + lane*4];
                acc.x += e0.x; acc.y += e0.y; acc.z += e0.z; acc.w += e0.w;
            }
        }
        int len = end - beg;
        float binv = (len > 0) ? (1.f / (float)len) : 0.f;
        acc.x *= binv; acc.y *= binv; acc.z *= binv; acc.w *= binv;
        *(float4*)&g_axh[(size_t)n*256 + lane*4] = acc;
        *(float4*)&g_axh[(size_t)n*256 + 128 + lane*4] = *(const float4*)&x[(size_t)n*128 + lane*4];
    }
}

// ---------------- merged bn_stats + hyper_out ----------------
__global__ void bn_hyper(const int* __restrict__ ei, const float* __restrict__ bh,
                         float* __restrict__ out2) {
    if (blockIdx.x < 256) {
        __shared__ float ssum[8][CC], ssq[8][CC];
        int c  = threadIdx.x & 31;
        int ry = threadIdx.x >> 5;
        float s = 0.f, q = 0.f;
        for (int r = blockIdx.x * 8 + ry; r < NN; r += 256 * 8) {
            float v = g_xgat[r*CC + c];
            s += v; q += v * v;
        }
        ssum[ry][c] = s; ssq[ry][c] = q;
        __syncthreads();
        if (ry == 0) {
            #pragma unroll
            for (int i = 1; i < 8; i++) { s += ssum[i][c]; q += ssq[i][c]; }
            atomicAdd(&g_sum[c],   (double)s);
            atomicAdd(&g_sumsq[c], (double)q);
        }
    } else {
        int idx = (blockIdx.x - 256) * 256 + threadIdx.x;
        if (idx >= E2*CC) return;
        int i = idx >> 5, c = idx & 31;
        out2[idx] = 0.5f * (g_o1[ei[i]*CC + c] + g_o1[ei[EE + i]*CC + c]) + bh[c];
    }
}

__global__ void bn_final() {
    int c = threadIdx.x;
    if (c < CC) {
        double mu  = g_sum[c] / (double)NN;
        double var = g_sumsq[c] / (double)NN - mu * mu;
        g_mu[c]   = (float)mu;
        g_rstd[c] = (float)(1.0 / sqrt(var + 1e-5));
    }
}

__global__ void bn_apply(const float* __restrict__ bn_w, const float* __restrict__ bn_b,
                         float* __restrict__ out1) {
    int i = blockIdx.x * blockDim.x + threadIdx.x;
    if (i >= NN*CC) return;
    int c = i & 31;
    float xn = bn_w[c] * (g_xgat[i] - g_mu[c]) * g_rstd[c] + bn_b[c];
    out1[i] = 0.5f * xn * (1.0f + erff(xn * 0.70710678118654752f));
}

// ---------------- launcher ----------------
extern "C" void kernel_launch(void* const* d_in, const int* in_sizes, int n_in,
                              void* d_out, int out_size) {
    const float* x    = (const float*)d_in[0];
    const float* ea   = (const float*)d_in[1];
    const float* Wq   = (const float*)d_in[2];
    const float* bq   = (const float*)d_in[3];
    const float* Wk   = (const float*)d_in[4];
    const float* bk   = (const float*)d_in[5];
    const float* Wv   = (const float*)d_in[6];
    const float* bv   = (const float*)d_in[7];
    const float* We2  = (const float*)d_in[8];
    const float* be2  = (const float*)d_in[9];
    const float* We3  = (const float*)d_in[10];
    const float* be3  = (const float*)d_in[11];
    const float* Wcon = (const float*)d_in[12];
    const float* bn_w = (const float*)d_in[13];
    const float* bn_b = (const float*)d_in[14];
    const float* Wh1  = (const float*)d_in[15];
    const float* Wh2  = (const float*)d_in[16];
    const float* bh   = (const float*)d_in[17];
    const int*   ei   = (const int*)d_in[18];

    float* out  = (float*)d_out;
    float* out1 = out;
    float* out2 = out + (size_t)NN * CC;

    float *pwqkv, *pbqkv;
    int *pcntA, *pcntH, *poffA, *poffH, *pcurA, *pcurH, *pblkA, *pblkH;
    cudaGetSymbolAddress((void**)&pwqkv, g_wqkv);
    cudaGetSymbolAddress((void**)&pbqkv, g_bqkv);
    cudaGetSymbolAddress((void**)&pcntA, g_cntA);
    cudaGetSymbolAddress((void**)&pcntH, g_cntH);
    cudaGetSymbolAddress((void**)&poffA, g_offA);
    cudaGetSymbolAddress((void**)&poffH, g_offH);
    cudaGetSymbolAddress((void**)&pcurA, g_curA);
    cudaGetSymbolAddress((void**)&pcurH, g_curH);
    cudaGetSymbolAddress((void**)&pblkA, g_blkA);
    cudaGetSymbolAddress((void**)&pblkH, g_blkH);

    const int U_SMEM = (128*132 + GN*128) * 4;
    cudaFuncSetAttribute(compute_u, cudaFuncAttributeMaxDynamicSharedMemorySize, U_SMEM);

    setup_kernel<<<256, 256>>>(We2, Wcon, We3, be3, Wh1, Wh2, Wq, bq, Wk, bk, Wv, bv);

    // CSR build
    csr_count<<<(EE + 255)/256, 256>>>(ei);
    scan1<<<NB_SCAN, 1024>>>(pcntA, poffA, pblkA);
    scan1<<<NB_SCAN, 1024>>>(pcntH, poffH, pblkH);
    scan2<<<1, 32>>>(pblkA);
    scan2<<<1, 32>>>(pblkH);
    scan3<<<(NN + 255)/256, 256>>>(poffA, pcurA, pblkA);
    scan3<<<(NN + 255)/256, 256>>>(poffH, pcurH, pblkH);
    csr_fill<<<(EE + 255)/256, 256>>>(ei);

    // fused qkv projection: q -> fp32, k/v -> fp16 packed
    gemm_bias<128,128,16,8,8,true><<<dim3(3, (NN + 127)/128), 256>>>(x, pwqkv, pbqkv, nullptr, NN, QS, DINF);

    // u precompute
    compute_u<<<(NN + GN - 1)/GN, 256, U_SMEM>>>();

    // fused attention + hyper aggregation (occ 3, fp16 kv)
    edge_fused<<<2 * ((NN + 7)/8), 256>>>(ei, ea, be2, x);

    // both output projections
    gemm_dual<<<dim3(1, 2*NB32), 256>>>();

    // bn stats + hyper edge output
    bn_hyper<<<256 + (E2*CC + 255)/256, 256>>>(ei, bh, out2);
    bn_final<<<1, 32>>>();
    bn_apply<<<(NN * CC + 255) / 256, 256>>>(bn_w, bn_b, out1);
}

// round 15
// speedup vs baseline: 1.4044x; 1.4044x over previous
#include <cuda_runtime.h>
#include <cuda_fp16.h>
#include <math.h>
#include <stdint.h>

#define NN 50000
#define EE 512000
#define E2 (EE/2)
#define DINF 128
#define HC 128
#define CC 32
#define HH 4
#define AYW 656   // 128 va | 512 y | 1 ind | 15 pad
#define QS 384
#define NB_SCAN ((NN + 1023) / 1024)

// ---------------- scratch ----------------
__device__ float    g_qf[(size_t)NN*HC];       // q fp32
__device__ __half   g_kv[(size_t)NN*256];      // [k | v] fp16
__device__ float    g_wqkv[DINF*QS];
__device__ float    g_bqkv[QS];
__device__ float    g_u[(size_t)NN*HH*DINF];
__device__ float    g_we2t[DINF*HC];
__device__ float    g_ay[(size_t)NN*AYW];
__device__ float    g_axh[(size_t)NN*256];
__device__ float    g_wbig[AYW*CC];
__device__ float    g_wh[256*CC];
__device__ float    g_xgat[NN*CC];
__device__ float    g_o1[NN*CC];
__device__ double   g_sum[CC];
__device__ double   g_sumsq[CC];
__device__ float    g_mu[CC];
__device__ float    g_rstd[CC];
// CSR
__device__ int      g_cntA[NN];
__device__ int      g_cntH[NN];
__device__ int      g_offA[NN+1];
__device__ int      g_offH[NN+1];
__device__ int      g_curA[NN];
__device__ int      g_curH[NN];
__device__ int      g_payA[EE];
__device__ int      g_payH[EE];
__device__ int      g_blkA[NB_SCAN+1];
__device__ int      g_blkH[NB_SCAN+1];

// ---------------- f32x2 helpers ----------------
__device__ __forceinline__ unsigned long long pack2(float lo, float hi) {
    unsigned long long r;
    asm("mov.b64 %0, {%1, %2};" : "=l"(r) : "f"(lo), "f"(hi));
    return r;
}
__device__ __forceinline__ void fma2(unsigned long long& d, unsigned long long a, unsigned long long b) {
    asm("fma.rn.f32x2 %0, %1, %2, %0;" : "+l"(d) : "l"(a), "l"(b));
}
__device__ __forceinline__ float2 unpack2(unsigned long long v) {
    float lo, hi;
    asm("mov.b64 {%0, %1}, %2;" : "=f"(lo), "=f"(hi) : "l"(v));
    return make_float2(lo, hi);
}

// ---------------- setup ----------------
__global__ void setup_kernel(const float* __restrict__ We2,
                             const float* __restrict__ Wcon, const float* __restrict__ We3,
                             const float* __restrict__ be3,
                             const float* __restrict__ Wh1, const float* __restrict__ Wh2,
                             const float* __restrict__ Wq, const float* __restrict__ bq,
                             const float* __restrict__ Wk, const float* __restrict__ bk,
                             const float* __restrict__ Wv, const float* __restrict__ bv) {
    int tid = blockIdx.x * blockDim.x + threadIdx.x;
    int stride = gridDim.x * blockDim.x;
    for (int j = tid; j < NN; j += stride) { g_cntA[j]=0; g_cntH[j]=0; }
    if (tid < CC) { g_sum[tid]=0.0; g_sumsq[tid]=0.0; }
    for (int i = tid; i < DINF*HC; i += stride) {
        int f = i >> 7, o = i & 127;
        g_we2t[o*DINF + f] = We2[i];
    }
    for (int idx = tid; idx < AYW*CC; idx += stride) {
        int r = idx / CC, c = idx % CC;
        float v;
        if (r < 128) {
            v = Wcon[r*CC + c];
        } else if (r < 640) {
            int h = (r - 128) >> 7, f = (r - 128) & 127;
            float a = 0.f;
            #pragma unroll
            for (int c2 = 0; c2 < 32; c2++)
                a = fmaf(We3[f*HC + h*32 + c2], Wcon[(h*32 + c2)*CC + c], a);
            v = a;
        } else if (r == 640) {
            float a = 0.f;
            for (int k = 0; k < HC; k++)
                a = fmaf(be3[k], Wcon[k*CC + c], a);
            v = a;
        } else v = 0.f;
        g_wbig[r*CC + c] = v;
    }
    for (int j = tid; j < 256*CC; j += stride) {
        int r = j / CC, c = j % CC;
        g_wh[r*CC + c] = (r < 128) ? Wh1[r*CC + c] : Wh2[(r-128)*CC + c];
    }
    for (int j = tid; j < DINF*QS; j += stride) {
        int f = j / QS, n = j % QS;
        float v = (n < 128) ? Wq[f*HC + n] : (n < 256) ? Wk[f*HC + n - 128] : Wv[f*HC + n - 256];
        g_wqkv[j] = v;
    }
    if (tid < QS) {
        g_bqkv[tid] = (tid < 128) ? bq[tid] : (tid < 256) ? bk[tid-128] : bv[tid-256];
    }
}

// ---------------- CSR build ----------------
__global__ void csr_count(const int* __restrict__ ei) {
    int i = blockIdx.x * blockDim.x + threadIdx.x;
    if (i >= EE) return;
    atomicAdd(&g_cntA[ei[EE + i]], 1);
    if (i < E2) {
        atomicAdd(&g_cntH[ei[i]],      1);
        atomicAdd(&g_cntH[ei[EE + i]], 1);
    }
}

// combined A+H scans: blockIdx.y selects which CSR
__global__ void scan1(int dummy) {
    __shared__ int sd[1024];
    const int* cnt = blockIdx.y ? g_cntH : g_cntA;
    int* off = blockIdx.y ? g_offH : g_offA;
    int* blk = blockIdx.y ? g_blkH : g_blkA;
    int tid = threadIdx.x;
    int i = blockIdx.x * 1024 + tid;
    int v = (i < NN) ? cnt[i] : 0;
    sd[tid] = v;
    __syncthreads();
    #pragma unroll
    for (int ofs = 1; ofs < 1024; ofs <<= 1) {
        int t = (tid >= ofs) ? sd[tid - ofs] : 0;
        __syncthreads();
        sd[tid] += t;
        __syncthreads();
    }
    if (i < NN) off[i] = sd[tid] - v;
    if (tid == 1023) blk[blockIdx.x] = sd[1023];
}

__global__ void scan2(int dummy) {
    int* blk = (threadIdx.x >= 32) ? g_blkH : g_blkA;
    if ((threadIdx.x & 31) == 0) {
        int run = 0;
        for (int b = 0; b < NB_SCAN; b++) { int t = blk[b]; blk[b] = run; run += t; }
        blk[NB_SCAN] = run;
    }
}

__global__ void scan3(int dummy) {
    int* off = blockIdx.y ? g_offH : g_offA;
    int* cur = blockIdx.y ? g_curH : g_curA;
    const int* blk = blockIdx.y ? g_blkH : g_blkA;
    int i = blockIdx.x * blockDim.x + threadIdx.x;
    if (i < NN) {
        int o = off[i] + blk[i >> 10];
        off[i] = o;
        cur[i] = o;
    }
    if (i == 0) off[NN] = blk[NB_SCAN];
}

__global__ void csr_fill(const int* __restrict__ ei) {
    int i = blockIdx.x * blockDim.x + threadIdx.x;
    if (i >= EE) return;
    int d = ei[EE + i];
    int pos = atomicAdd(&g_curA[d], 1);
    g_payA[pos] = i;
    if (i < E2) {
        int p1 = atomicAdd(&g_curH[ei[i]], 1);
        g_payH[p1] = i;
        int p2 = atomicAdd(&g_curH[ei[EE + i]], 1);
        g_payH[p2] = i;
    }
}

// ---------------- double-buffered SGEMM (f32x2), R13-proven version ----------------
template<int BM, int BN, int BK, int TM, int TN, bool QKV = false>
__global__ void __launch_bounds__((BM/TM)*(BN/TN), 2)
gemm_bias(const float* __restrict__ A, const float* __restrict__ W,
          const float* __restrict__ bias, float* __restrict__ C,
          int M, int N, int K) {
    constexpr int THREADS = (BM/TM)*(BN/TN);
    constexpr int A4 = BM*BK/4;
    constexpr int W4 = BK*BN/4;
    constexpr int AI = (A4 + THREADS - 1)/THREADS;
    constexpr int WI = (W4 + THREADS - 1)/THREADS;
    __shared__ float As[2][BK][BM+4];
    __shared__ float Ws[2][BK][BN];
    const int tid  = threadIdx.x;
    const int brow = blockIdx.y * BM;
    const int bcol = blockIdx.x * BN;
    const int trow = (tid / (BN/TN)) * TM;
    const int tcol = (tid % (BN/TN)) * TN;

    float4 stA[AI];
    float4 stW[WI];

    auto loadg = [&](int k0) {
        #pragma unroll
        for (int it = 0; it < AI; it++) {
            int i = tid + it*THREADS;
            if (i < A4) {
                int m = i / (BK/4), k4 = i % (BK/4);
                int gm = brow + m;
                stA[it] = (gm < M) ? *(const float4*)(A + (size_t)gm*K + k0 + k4*4)
                                   : make_float4(0.f,0.f,0.f,0.f);
            }
        }
        #pragma unroll
        for (int it = 0; it < WI; it++) {
            int i = tid + it*THREADS;
            if (i < W4) {
                int kk = i / (BN/4), n4 = i % (BN/4);
                stW[it] = *(const float4*)(W + (size_t)(k0+kk)*N + bcol + n4*4);
            }
        }
    };
    auto store_s = [&](int buf) {
        #pragma unroll
        for (int it = 0; it < AI; it++) {
            int i = tid + it*THREADS;
            if (i < A4) {
                int m = i / (BK/4), k4 = i % (BK/4);
                As[buf][k4*4+0][m] = stA[it].x;
                As[buf][k4*4+1][m] = stA[it].y;
                As[buf][k4*4+2][m] = stA[it].z;
                As[buf][k4*4+3][m] = stA[it].w;
            }
        }
        #pragma unroll
        for (int it = 0; it < WI; it++) {
            int i = tid + it*THREADS;
            if (i < W4) {
                int kk = i / (BN/4), n4 = i % (BN/4);
                *(float4*)&Ws[buf][kk][n4*4] = stW[it];
            }
        }
    };

    unsigned long long acc2[TM][TN/2];
    #pragma unroll
    for (int i = 0; i < TM; i++)
        #pragma unroll
        for (int j = 0; j < TN/2; j++) acc2[i][j] = 0ULL;

    const int nt = K / BK;
    loadg(0);
    store_s(0);
    __syncthreads();

    for (int t = 0; t < nt; t++) {
        int cur = t & 1;
        if (t + 1 < nt) loadg((t+1)*BK);
        #pragma unroll
        for (int kk = 0; kk < BK; kk++) {
            float ra[TM], rb[TN];
            #pragma unroll
            for (int i = 0; i < TM; i += 4)
                *(float4*)&ra[i] = *(const float4*)&As[cur][kk][trow + i];
            #pragma unroll
            for (int j = 0; j < TN; j += 4)
                *(float4*)&rb[j] = *(const float4*)&Ws[cur][kk][tcol + j];
            unsigned long long rbp[TN/2];
            #pragma unroll
            for (int j = 0; j < TN/2; j++) rbp[j] = pack2(rb[2*j], rb[2*j+1]);
            #pragma unroll
            for (int i = 0; i < TM; i++) {
                unsigned long long aa = pack2(ra[i], ra[i]);
                #pragma unroll
                for (int j = 0; j < TN/2; j++)
                    fma2(acc2[i][j], aa, rbp[j]);
            }
        }
        if (t + 1 < nt) {
            store_s((t+1) & 1);
            __syncthreads();
        }
    }

    #pragma unroll
    for (int i = 0; i < TM; i++) {
        int gm = brow + trow + i;
        if (gm >= M) continue;
        #pragma unroll
        for (int j = 0; j < TN; j += 4) {
            int gn = bcol + tcol + j;
            float2 p0 = unpack2(acc2[i][j/2]);
            float2 p1 = unpack2(acc2[i][j/2 + 1]);
            float4 v;
            v.x = p0.x + (bias ? bias[gn+0] : 0.f);
            v.y = p0.y + (bias ? bias[gn+1] : 0.f);
            v.z = p1.x + (bias ? bias[gn+2] : 0.f);
            v.w = p1.y + (bias ? bias[gn+3] : 0.f);
            if constexpr (QKV) {
                if (bcol == 0) {
                    *(float4*)(g_qf + (size_t)gm*HC + gn) = v;
                } else {
                    __half h[4];
                    h[0] = __float2half_rn(v.x); h[1] = __float2half_rn(v.y);
                    h[2] = __float2half_rn(v.z); h[3] = __float2half_rn(v.w);
                    *(uint2*)(g_kv + (size_t)gm*256 + (gn - 128)) = *(uint2*)h;
                }
            } else {
                *(float4*)(C + (size_t)gm*N + gn) = v;
            }
        }
    }
}

// ---------------- dual small GEMM (N=32), R13-proven version ----------------
__device__ __forceinline__ void gemm_body32(const float* __restrict__ A, const float* __restrict__ W,
                                            float* __restrict__ C, int K, int browblk) {
    __shared__ float As[2][16][132];
    __shared__ float Ws[2][16][32];
    const int tid  = threadIdx.x;
    const int brow = browblk * 128;
    const int trow = (tid / 8) * 4;
    const int tcol = (tid % 8) * 4;

    float4 stA[2];
    float4 stW;

    auto loadg = [&](int k0) {
        #pragma unroll
        for (int it = 0; it < 2; it++) {
            int i = tid + it*256;
            int m = i / 4, k4 = i % 4;
            int gm = brow + m;
            stA[it] = (gm < NN) ? *(const float4*)(A + (size_t)gm*K + k0 + k4*4)
                                : make_float4(0.f,0.f,0.f,0.f);
        }
        if (tid < 128) {
            int kk = tid / 8, n4 = tid % 8;
            stW = *(const float4*)(W + (size_t)(k0+kk)*32 + n4*4);
        }
    };
    auto store_s = [&](int buf) {
        #pragma unroll
        for (int it = 0; it < 2; it++) {
            int i = tid + it*256;
            int m = i / 4, k4 = i % 4;
            As[buf][k4*4+0][m] = stA[it].x;
            As[buf][k4*4+1][m] = stA[it].y;
            As[buf][k4*4+2][m] = stA[it].z;
            As[buf][k4*4+3][m] = stA[it].w;
        }
        if (tid < 128) {
            int kk = tid / 8, n4 = tid % 8;
            *(float4*)&Ws[buf][kk][n4*4] = stW;
        }
    };

    unsigned long long acc2[4][2];
    #pragma unroll
    for (int i = 0; i < 4; i++) { acc2[i][0] = 0ULL; acc2[i][1] = 0ULL; }

    const int nt = K / 16;
    loadg(0);
    store_s(0);
    __syncthreads();

    for (int t = 0; t < nt; t++) {
        int cur = t & 1;
        if (t + 1 < nt) loadg((t+1)*16);
        #pragma unroll
        for (int kk = 0; kk < 16; kk++) {
            float ra[4], rb[4];
            *(float4*)&ra[0] = *(const float4*)&As[cur][kk][trow];
            *(float4*)&rb[0] = *(const float4*)&Ws[cur][kk][tcol];
            unsigned long long rbp0 = pack2(rb[0], rb[1]);
            unsigned long long rbp1 = pack2(rb[2], rb[3]);
            #pragma unroll
            for (int i = 0; i < 4; i++) {
                unsigned long long aa = pack2(ra[i], ra[i]);
                fma2(acc2[i][0], aa, rbp0);
                fma2(acc2[i][1], aa, rbp1);
            }
        }
        if (t + 1 < nt) {
            store_s((t+1) & 1);
            __syncthreads();
        }
    }

    #pragma unroll
    for (int i = 0; i < 4; i++) {
        int gm = brow + trow + i;
        if (gm >= NN) continue;
        float2 p0 = unpack2(acc2[i][0]);
        float2 p1 = unpack2(acc2[i][1]);
        float4 v = make_float4(p0.x, p0.y, p1.x, p1.y);
        *(float4*)(C + (size_t)gm*32 + tcol) = v;
    }
}

#define NB32 ((NN + 127) / 128)
__global__ void __launch_bounds__(256, 2) gemm_dual() {
    bool second = blockIdx.y >= NB32;
    const float* A = second ? g_axh : g_ay;
    const float* W = second ? g_wh  : g_wbig;
    float*       C = second ? g_o1  : g_xgat;
    int          K = second ? 256   : AYW;
    int        blk = second ? (blockIdx.y - NB32) : blockIdx.y;
    gemm_body32(A, W, C, K, blk);
}

// ---------------- u precompute ----------------
#define GN 32
__global__ void compute_u() {
    extern __shared__ float shm[];
    float (*sW)[132] = (float (*)[132])shm;
    float (*sq)[128] = (float (*)[128])(shm + 128*132);
    int tid = threadIdx.x;
    int n0 = blockIdx.x * GN;
    for (int i = tid; i < 128*128; i += 256) {
        int o = i >> 7, f = i & 127;
        sW[o][f] = g_we2t[i];
    }
    for (int i = tid; i < GN*128; i += 256) {
        int nl = i >> 7, c = i & 127;
        int n = n0 + nl;
        sq[nl][c] = (n < NN) ? g_qf[(size_t)n*HC + c] : 0.f;
    }
    __syncthreads();
    int w = tid >> 5, lane = tid & 31;
    for (int p = w; p < GN*HH; p += 8) {
        int nl = p >> 2, h = p & 3;
        int n = n0 + nl;
        if (n >= NN) continue;
        float a0=0.f, a1=0.f, a2=0.f, a3=0.f;
        #pragma unroll
        for (int c = 0; c < 32; c++) {
            float qv = sq[nl][h*32 + c];
            const float* row = sW[h*32 + c];
            a0 = fmaf(qv, row[lane],      a0);
            a1 = fmaf(qv, row[lane + 32], a1);
            a2 = fmaf(qv, row[lane + 64], a2);
            a3 = fmaf(qv, row[lane + 96], a3);
        }
        size_t base = (size_t)n*512 + h*128;
        g_u[base + lane]      = a0;
        g_u[base + lane + 32] = a1;
        g_u[base + lane + 64] = a2;
        g_u[base + lane + 96] = a3;
    }
}

// ---------------- fused edge kernel: u in smem, occ 3, fp16 kv gathers (R13-proven) ----------------
__global__ void __launch_bounds__(256, 3)
edge_fused(const int* __restrict__ ei, const float* __restrict__ ea,
           const float* __restrict__ be2, const float* __restrict__ x) {
    const unsigned FULL = 0xffffffffu;
    __shared__ float su[8][4][132];
    const int lane = threadIdx.x & 31;
    const int w = threadIdx.x >> 5;
    const int node = (blockIdx.x >> 1) * 8 + w;
    if (node >= NN) return;

    if ((blockIdx.x & 1) == 0) {
        const int g = lane >> 3, sub = lane & 7;
        const int d = node;
        const int beg = g_offA[d], end = g_offA[d+1];
        const float scale = 0.17677669529663687f;

        float4 qv = *(const float4*)&g_qf[(size_t)d*HC + g*32 + sub*4];
        float4 b2 = *(const float4*)&be2[g*32 + sub*4];
        float qb2 = qv.x*b2.x + qv.y*b2.y + qv.z*b2.z + qv.w*b2.w;
        #pragma unroll
        for (int j = 0; j < 4; j++) {
            float4 t = *(const float4*)&g_u[(size_t)d*512 + g*128 + sub*16 + j*4];
            *(float4*)&su[w][j][lane*4] = t;
        }
        __syncwarp();

        unsigned long long vaP0 = 0ULL, vaP1 = 0ULL;
        unsigned long long y0P0 = 0ULL, y0P1 = 0ULL;
        unsigned long long y1P0 = 0ULL, y1P1 = 0ULL;
        unsigned long long y2P0 = 0ULL, y2P1 = 0ULL;
        unsigned long long y3P0 = 0ULL, y3P1 = 0ULL;
        float s1 = 0.f, s20 = 0.f, s21 = 0.f, s22 = 0.f, s23 = 0.f;

        for (int base = beg; base < end; base += 32) {
            int m = end - base; if (m > 32) m = 32;
            int eL = 0, sL = 0;
            if (base + lane < end) {
                eL = g_payA[base + lane];
                sL = ei[eL];
            }
            int it = 0;
            for (; it + 1 < m; it += 2) {
                int e0 = __shfl_sync(FULL, eL, it),   s0  = __shfl_sync(FULL, sL, it);
                int e1 = __shfl_sync(FULL, eL, it+1), s1i = __shfl_sync(FULL, sL, it+1);
                const float* eb0 = ea + (size_t)e0*128;
                const float* eb1 = ea + (size_t)e1*128;
                const __half* kv0 = g_kv + (size_t)s0*256;
                const __half* kv1 = g_kv + (size_t)s1i*256;

                uint2 kr0 = *(const uint2*)(kv0 + g*32 + sub*4);
                uint2 kr1 = *(const uint2*)(kv1 + g*32 + sub*4);
                float2 t;
                t = __half22float2(*(__half2*)&kr0.x);
                float p1a = qv.x*t.x + qv.y*t.y;
                t = __half22float2(*(__half2*)&kr0.y);
                p1a += qv.z*t.x + qv.w*t.y;
                t = __half22float2(*(__half2*)&kr1.x);
                float p1b = qv.x*t.x + qv.y*t.y;
                t = __half22float2(*(__half2*)&kr1.y);
                p1b += qv.z*t.x + qv.w*t.y;
                float p2a = qb2, p2b = qb2;
                #pragma unroll
                for (int j = 0; j < 4; j++) {
                    float4 uj = *(const float4*)&su[w][j][lane*4];
                    float4 ev0 = *(const float4*)&eb0[sub*16 + j*4];
                    float4 ev1 = *(const float4*)&eb1[sub*16 + j*4];
                    p2a += ev0.x*uj.x + ev0.y*uj.y + ev0.z*uj.z + ev0.w*uj.w;
                    p2b += ev1.x*uj.x + ev1.y*uj.y + ev1.z*uj.z + ev1.w*uj.w;
                }
                #pragma unroll
                for (int o = 1; o < 8; o <<= 1) {
                    p1a += __shfl_xor_sync(FULL, p1a, o);
                    p2a += __shfl_xor_sync(FULL, p2a, o);
                    p1b += __shfl_xor_sync(FULL, p1b, o);
                    p2b += __shfl_xor_sync(FULL, p2b, o);
                }
                float ex1a = __expf(p1a * scale), ex2a = __expf(p2a * scale);
                float ex1b = __expf(p1b * scale), ex2b = __expf(p2b * scale);
                s1 += ex1a + ex1b;
                float e20a = __shfl_sync(FULL, ex2a, 0),  e20b = __shfl_sync(FULL, ex2b, 0);
                float e21a = __shfl_sync(FULL, ex2a, 8),  e21b = __shfl_sync(FULL, ex2b, 8);
                float e22a = __shfl_sync(FULL, ex2a, 16), e22b = __shfl_sync(FULL, ex2b, 16);
                float e23a = __shfl_sync(FULL, ex2a, 24), e23b = __shfl_sync(FULL, ex2b, 24);
                s20 += e20a + e20b; s21 += e21a + e21b;
                s22 += e22a + e22b; s23 += e23a + e23b;

                float4 ey0 = *(const float4*)&eb0[lane*4];
                float4 ey1 = *(const float4*)&eb1[lane*4];
                uint2 vr0 = *(const uint2*)(kv0 + 128 + lane*4);
                uint2 vr1 = *(const uint2*)(kv1 + 128 + lane*4);
                unsigned long long ey0lo = pack2(ey0.x, ey0.y), ey0hi = pack2(ey0.z, ey0.w);
                unsigned long long ey1lo = pack2(ey1.x, ey1.y), ey1hi = pack2(ey1.z, ey1.w);
                unsigned long long x1a = pack2(ex1a, ex1a), x1b = pack2(ex1b, ex1b);
                t = __half22float2(*(__half2*)&vr0.x);
                fma2(vaP0, x1a, pack2(t.x, t.y));
                t = __half22float2(*(__half2*)&vr0.y);
                fma2(vaP1, x1a, pack2(t.x, t.y));
                t = __half22float2(*(__half2*)&vr1.x);
                fma2(vaP0, x1b, pack2(t.x, t.y));
                t = __half22float2(*(__half2*)&vr1.y);
                fma2(vaP1, x1b, pack2(t.x, t.y));
                unsigned long long c0a = pack2(e20a, e20a), c0b = pack2(e20b, e20b);
                fma2(y0P0, c0a, ey0lo); fma2(y0P0, c0b, ey1lo);
                fma2(y0P1, c0a, ey0hi); fma2(y0P1, c0b, ey1hi);
                unsigned long long c1a = pack2(e21a, e21a), c1b = pack2(e21b, e21b);
                fma2(y1P0, c1a, ey0lo); fma2(y1P0, c1b, ey1lo);
                fma2(y1P1, c1a, ey0hi); fma2(y1P1, c1b, ey1hi);
                unsigned long long c2a = pack2(e22a, e22a), c2b = pack2(e22b, e22b);
                fma2(y2P0, c2a, ey0lo); fma2(y2P0, c2b, ey1lo);
                fma2(y2P1, c2a, ey0hi); fma2(y2P1, c2b, ey1hi);
                unsigned long long c3a = pack2(e23a, e23a), c3b = pack2(e23b, e23b);
                fma2(y3P0, c3a, ey0lo); fma2(y3P0, c3b, ey1lo);
                fma2(y3P1, c3a, ey0hi); fma2(y3P1, c3b, ey1hi);
            }
            if (it < m) {
                int e0 = __shfl_sync(FULL, eL, it), s0 = __shfl_sync(FULL, sL, it);
                const float* eb0 = ea + (size_t)e0*128;
                const __half* kv0 = g_kv + (size_t)s0*256;
                uint2 kr0 = *(const uint2*)(kv0 + g*32 + sub*4);
                float2 t;
                t = __half22float2(*(__half2*)&kr0.x);
                float p1a = qv.x*t.x + qv.y*t.y;
                t = __half22float2(*(__half2*)&kr0.y);
                p1a += qv.z*t.x + qv.w*t.y;
                float p2a = qb2;
                #pragma unroll
                for (int j = 0; j < 4; j++) {
                    float4 uj = *(const float4*)&su[w][j][lane*4];
                    float4 ev0 = *(const float4*)&eb0[sub*16 + j*4];
                    p2a += ev0.x*uj.x + ev0.y*uj.y + ev0.z*uj.z + ev0.w*uj.w;
                }
                #pragma unroll
                for (int o = 1; o < 8; o <<= 1) {
                    p1a += __shfl_xor_sync(FULL, p1a, o);
                    p2a += __shfl_xor_sync(FULL, p2a, o);
                }
                float ex1a = __expf(p1a * scale), ex2a = __expf(p2a * scale);
                s1 += ex1a;
                float e20a = __shfl_sync(FULL, ex2a, 0);
                float e21a = __shfl_sync(FULL, ex2a, 8);
                float e22a = __shfl_sync(FULL, ex2a, 16);
                float e23a = __shfl_sync(FULL, ex2a, 24);
                s20 += e20a; s21 += e21a; s22 += e22a; s23 += e23a;
                float4 ey0 = *(const float4*)&eb0[lane*4];
                uint2 vr0 = *(const uint2*)(kv0 + 128 + lane*4);
                unsigned long long ey0lo = pack2(ey0.x, ey0.y), ey0hi = pack2(ey0.z, ey0.w);
                unsigned long long x1a = pack2(ex1a, ex1a);
                t = __half22float2(*(__half2*)&vr0.x);
                fma2(vaP0, x1a, pack2(t.x, t.y));
                t = __half22float2(*(__half2*)&vr0.y);
                fma2(vaP1, x1a, pack2(t.x, t.y));
                unsigned long long c0a = pack2(e20a, e20a);
                fma2(y0P0, c0a, ey0lo); fma2(y0P1, c0a, ey0hi);
                unsigned long long c1a = pack2(e21a, e21a);
                fma2(y1P0, c1a, ey0lo); fma2(y1P1, c1a, ey0hi);
                unsigned long long c2a = pack2(e22a, e22a);
                fma2(y2P0, c2a, ey0lo); fma2(y2P1, c2a, ey0hi);
                unsigned long long c3a = pack2(e23a, e23a);
                fma2(y3P0, c3a, ey0lo); fma2(y3P1, c3a, ey0hi);
            }
        }

        float r1 = 1.f / (s1 + 1e-16f);
        float q0 = 1.f/(s20+1e-16f), q1 = 1.f/(s21+1e-16f);
        float q2 = 1.f/(s22+1e-16f), q3 = 1.f/(s23+1e-16f);
        float2 a, b;
        float* row = g_ay + (size_t)d*AYW;
        a = unpack2(vaP0); b = unpack2(vaP1);
        *(float4*)&row[lane*4] = make_float4(a.x*r1, a.y*r1, b.x*r1, b.y*r1);
        a = unpack2(y0P0); b = unpack2(y0P1);
        *(float4*)&row[128 + 0*128 + lane*4] = make_float4(a.x*q0, a.y*q0, b.x*q0, b.y*q0);
        a = unpack2(y1P0); b = unpack2(y1P1);
        *(float4*)&row[128 + 1*128 + lane*4] = make_float4(a.x*q1, a.y*q1, b.x*q1, b.y*q1);
        a = unpack2(y2P0); b = unpack2(y2P1);
        *(float4*)&row[128 + 2*128 + lane*4] = make_float4(a.x*q2, a.y*q2, b.x*q2, b.y*q2);
        a = unpack2(y3P0); b = unpack2(y3P1);
        *(float4*)&row[128 + 3*128 + lane*4] = make_float4(a.x*q3, a.y*q3, b.x*q3, b.y*q3);
        if (lane == 0)      row[640] = (end > beg) ? 1.f : 0.f;
        else if (lane < 16) row[640 + lane] = 0.f;
    } else {
        const int n = node;
        const int beg = g_offH[n], end = g_offH[n+1];
        float4 acc = make_float4(0.f,0.f,0.f,0.f);
        for (int base = beg; base < end; base += 32) {
            int m = end - base; if (m > 32) m = 32;
            int iL = 0;
            if (base + lane < end) iL = g_payH[base + lane];
            int it = 0;
            for (; it + 1 < m; it += 2) {
                int i0 = __shfl_sync(FULL, iL, it);
                int i1 = __shfl_sync(FULL, iL, it+1);
                float4 e0 = *(const float4*)&ea[(size_t)i0*128 + lane*4];
                float4 e1 = *(const float4*)&ea[(size_t)i1*128 + lane*4];
                acc.x += e0.x + e1.x; acc.y += e0.y + e1.y;
                acc.z += e0.z + e1.z; acc.w += e0.w + e1.w;
            }
            if (it < m) {
                int i0 = __shfl_sync(FULL, iL, it);
                float4 e0 = *(const float4*)&ea[(size_t)i0*128 + lane*4];
                acc.x += e0.x; acc.y += e0.y; acc.z += e0.z; acc.w += e0.w;
            }
        }
        int len = end - beg;
        float binv = (len > 0) ? (1.f / (float)len) : 0.f;
        acc.x *= binv; acc.y *= binv; acc.z *= binv; acc.w *= binv;
        *(float4*)&g_axh[(size_t)n*256 + lane*4] = acc;
        *(float4*)&g_axh[(size_t)n*256 + 128 + lane*4] = *(const float4*)&x[(size_t)n*128 + lane*4];
    }
}

// ---------------- merged bn_stats + hyper_out ----------------
__global__ void bn_hyper(const int* __restrict__ ei, const float* __restrict__ bh,
                         float* __restrict__ out2) {
    if (blockIdx.x < 256) {
        __shared__ float ssum[8][CC], ssq[8][CC];
        int c  = threadIdx.x & 31;
        int ry = threadIdx.x >> 5;
        float s = 0.f, q = 0.f;
        for (int r = blockIdx.x * 8 + ry; r < NN; r += 256 * 8) {
            float v = g_xgat[r*CC + c];
            s += v; q += v * v;
        }
        ssum[ry][c] = s; ssq[ry][c] = q;
        __syncthreads();
        if (ry == 0) {
            #pragma unroll
            for (int i = 1; i < 8; i++) { s += ssum[i][c]; q += ssq[i][c]; }
            atomicAdd(&g_sum[c],   (double)s);
            atomicAdd(&g_sumsq[c], (double)q);
        }
    } else {
        int idx = (blockIdx.x - 256) * 256 + threadIdx.x;
        if (idx >= E2*CC) return;
        int i = idx >> 5, c = idx & 31;
        out2[idx] = 0.5f * (g_o1[ei[i]*CC + c] + g_o1[ei[EE + i]*CC + c]) + bh[c];
    }
}

__global__ void bn_final() {
    int c = threadIdx.x;
    if (c < CC) {
        double mu  = g_sum[c] / (double)NN;
        double var = g_sumsq[c] / (double)NN - mu * mu;
        g_mu[c]   = (float)mu;
        g_rstd[c] = (float)(1.0 / sqrt(var + 1e-5));
    }
}

__global__ void bn_apply(const float* __restrict__ bn_w, const float* __restrict__ bn_b,
                         float* __restrict__ out1) {
    int i = blockIdx.x * blockDim.x + threadIdx.x;
    if (i >= NN*CC) return;
    int c = i & 31;
    float xn = bn_w[c] * (g_xgat[i] - g_mu[c]) * g_rstd[c] + bn_b[c];
    out1[i] = 0.5f * xn * (1.0f + erff(xn * 0.70710678118654752f));
}

// ---------------- launcher ----------------
extern "C" void kernel_launch(void* const* d_in, const int* in_sizes, int n_in,
                              void* d_out, int out_size) {
    const float* x    = (const float*)d_in[0];
    const float* ea   = (const float*)d_in[1];
    const float* Wq   = (const float*)d_in[2];
    const float* bq   = (const float*)d_in[3];
    const float* Wk   = (const float*)d_in[4];
    const float* bk   = (const float*)d_in[5];
    const float* Wv   = (const float*)d_in[6];
    const float* bv   = (const float*)d_in[7];
    const float* We2  = (const float*)d_in[8];
    const float* be2  = (const float*)d_in[9];
    const float* We3  = (const float*)d_in[10];
    const float* be3  = (const float*)d_in[11];
    const float* Wcon = (const float*)d_in[12];
    const float* bn_w = (const float*)d_in[13];
    const float* bn_b = (const float*)d_in[14];
    const float* Wh1  = (const float*)d_in[15];
    const float* Wh2  = (const float*)d_in[16];
    const float* bh   = (const float*)d_in[17];
    const int*   ei   = (const int*)d_in[18];

    float* out  = (float*)d_out;
    float* out1 = out;
    float* out2 = out + (size_t)NN * CC;

    float *pwqkv, *pbqkv;
    cudaGetSymbolAddress((void**)&pwqkv, g_wqkv);
    cudaGetSymbolAddress((void**)&pbqkv, g_bqkv);

    const int U_SMEM = (128*132 + GN*128) * 4;
    cudaFuncSetAttribute(compute_u, cudaFuncAttributeMaxDynamicSharedMemorySize, U_SMEM);

    setup_kernel<<<256, 256>>>(We2, Wcon, We3, be3, Wh1, Wh2, Wq, bq, Wk, bk, Wv, bv);

    // CSR build (A+H combined launches)
    csr_count<<<(EE + 255)/256, 256>>>(ei);
    scan1<<<dim3(NB_SCAN, 2), 1024>>>(0);
    scan2<<<1, 64>>>(0);
    scan3<<<dim3((NN + 255)/256, 2), 256>>>(0);
    csr_fill<<<(EE + 255)/256, 256>>>(ei);

    // fused qkv projection: q -> fp32, k/v -> fp16 packed
    gemm_bias<128,128,16,8,8,true><<<dim3(3, (NN + 127)/128), 256>>>(x, pwqkv, pbqkv, nullptr, NN, QS, DINF);

    // u precompute
    compute_u<<<(NN + GN - 1)/GN, 256, U_SMEM>>>();

    // fused attention + hyper aggregation (occ 3, fp16 kv)
    edge_fused<<<2 * ((NN + 7)/8), 256>>>(ei, ea, be2, x);

    // both output projections
    gemm_dual<<<dim3(1, 2*NB32), 256>>>();

    // bn stats + hyper edge output
    bn_hyper<<<256 + (E2*CC + 255)/256, 256>>>(ei, bh, out2);
    bn_final<<<1, 32>>>();
    bn_apply<<<(NN * CC + 255) / 256, 256>>>(bn_w, bn_b, out1);
}

// round 16
// speedup vs baseline: 1.4877x; 1.0593x over previous
#include <cuda_runtime.h>
#include <cuda_fp16.h>
#include <math.h>
#include <stdint.h>

#define NN 50000
#define EE 512000
#define E2 (EE/2)
#define DINF 128
#define HC 128
#define CC 32
#define HH 4
#define AYW 656   // 128 va | 512 y | 1 ind | 15 pad
#define QS 384
#define NB_SCAN ((NN + 1023) / 1024)

// ---------------- scratch ----------------
__device__ float    g_qf[(size_t)NN*HC];       // q fp32
__device__ __half   g_kv[(size_t)NN*256];      // [k | v] fp16
__device__ float    g_wqkv[DINF*QS];
__device__ float    g_bqkv[QS];
__device__ float    g_u[(size_t)NN*HH*DINF];
__device__ float    g_we2t[DINF*HC];
__device__ float    g_ay[(size_t)NN*AYW];
__device__ float    g_axh[(size_t)NN*256];
__device__ float    g_wbig[AYW*CC];
__device__ float    g_wh[256*CC];
__device__ float    g_xgat[NN*CC];
__device__ float    g_o1[NN*CC];
__device__ double   g_sum[CC];
__device__ double   g_sumsq[CC];
__device__ float    g_mu[CC];
__device__ float    g_rstd[CC];
// CSR
__device__ int      g_cntA[NN];
__device__ int      g_cntH[NN];
__device__ int      g_offA[NN+1];
__device__ int      g_offH[NN+1];
__device__ int      g_curA[NN];
__device__ int      g_curH[NN];
__device__ int      g_payA[EE];
__device__ int      g_payH[EE];
__device__ int      g_blkA[NB_SCAN+1];
__device__ int      g_blkH[NB_SCAN+1];

// ---------------- f32x2 helpers ----------------
__device__ __forceinline__ unsigned long long pack2(float lo, float hi) {
    unsigned long long r;
    asm("mov.b64 %0, {%1, %2};" : "=l"(r) : "f"(lo), "f"(hi));
    return r;
}
__device__ __forceinline__ void fma2(unsigned long long& d, unsigned long long a, unsigned long long b) {
    asm("fma.rn.f32x2 %0, %1, %2, %0;" : "+l"(d) : "l"(a), "l"(b));
}
__device__ __forceinline__ float2 unpack2(unsigned long long v) {
    float lo, hi;
    asm("mov.b64 {%0, %1}, %2;" : "=f"(lo), "=f"(hi) : "l"(v));
    return make_float2(lo, hi);
}

// ---------------- setup ----------------
__global__ void setup_kernel(const float* __restrict__ We2,
                             const float* __restrict__ Wcon, const float* __restrict__ We3,
                             const float* __restrict__ be3,
                             const float* __restrict__ Wh1, const float* __restrict__ Wh2,
                             const float* __restrict__ Wq, const float* __restrict__ bq,
                             const float* __restrict__ Wk, const float* __restrict__ bk,
                             const float* __restrict__ Wv, const float* __restrict__ bv) {
    int tid = blockIdx.x * blockDim.x + threadIdx.x;
    int stride = gridDim.x * blockDim.x;
    for (int j = tid; j < NN; j += stride) { g_cntA[j]=0; g_cntH[j]=0; }
    if (tid < CC) { g_sum[tid]=0.0; g_sumsq[tid]=0.0; }
    for (int i = tid; i < DINF*HC; i += stride) {
        int f = i >> 7, o = i & 127;
        g_we2t[o*DINF + f] = We2[i];
    }
    for (int idx = tid; idx < AYW*CC; idx += stride) {
        int r = idx / CC, c = idx % CC;
        float v;
        if (r < 128) {
            v = Wcon[r*CC + c];
        } else if (r < 640) {
            int h = (r - 128) >> 7, f = (r - 128) & 127;
            float a = 0.f;
            #pragma unroll
            for (int c2 = 0; c2 < 32; c2++)
                a = fmaf(We3[f*HC + h*32 + c2], Wcon[(h*32 + c2)*CC + c], a);
            v = a;
        } else if (r == 640) {
            float a = 0.f;
            for (int k = 0; k < HC; k++)
                a = fmaf(be3[k], Wcon[k*CC + c], a);
            v = a;
        } else v = 0.f;
        g_wbig[r*CC + c] = v;
    }
    for (int j = tid; j < 256*CC; j += stride) {
        int r = j / CC, c = j % CC;
        g_wh[r*CC + c] = (r < 128) ? Wh1[r*CC + c] : Wh2[(r-128)*CC + c];
    }
    for (int j = tid; j < DINF*QS; j += stride) {
        int f = j / QS, n = j % QS;
        float v = (n < 128) ? Wq[f*HC + n] : (n < 256) ? Wk[f*HC + n - 128] : Wv[f*HC + n - 256];
        g_wqkv[j] = v;
    }
    if (tid < QS) {
        g_bqkv[tid] = (tid < 128) ? bq[tid] : (tid < 256) ? bk[tid-128] : bv[tid-256];
    }
}

// ---------------- CSR build ----------------
__global__ void csr_count(const int* __restrict__ ei) {
    int i = blockIdx.x * blockDim.x + threadIdx.x;
    if (i >= EE) return;
    atomicAdd(&g_cntA[ei[EE + i]], 1);
    if (i < E2) {
        atomicAdd(&g_cntH[ei[i]],      1);
        atomicAdd(&g_cntH[ei[EE + i]], 1);
    }
}

__global__ void scan1(int dummy) {
    __shared__ int sd[1024];
    const int* cnt = blockIdx.y ? g_cntH : g_cntA;
    int* off = blockIdx.y ? g_offH : g_offA;
    int* blk = blockIdx.y ? g_blkH : g_blkA;
    int tid = threadIdx.x;
    int i = blockIdx.x * 1024 + tid;
    int v = (i < NN) ? cnt[i] : 0;
    sd[tid] = v;
    __syncthreads();
    #pragma unroll
    for (int ofs = 1; ofs < 1024; ofs <<= 1) {
        int t = (tid >= ofs) ? sd[tid - ofs] : 0;
        __syncthreads();
        sd[tid] += t;
        __syncthreads();
    }
    if (i < NN) off[i] = sd[tid] - v;
    if (tid == 1023) blk[blockIdx.x] = sd[1023];
}

__global__ void scan2(int dummy) {
    int* blk = (threadIdx.x >= 32) ? g_blkH : g_blkA;
    if ((threadIdx.x & 31) == 0) {
        int run = 0;
        for (int b = 0; b < NB_SCAN; b++) { int t = blk[b]; blk[b] = run; run += t; }
        blk[NB_SCAN] = run;
    }
}

__global__ void scan3(int dummy) {
    int* off = blockIdx.y ? g_offH : g_offA;
    int* cur = blockIdx.y ? g_curH : g_curA;
    const int* blk = blockIdx.y ? g_blkH : g_blkA;
    int i = blockIdx.x * blockDim.x + threadIdx.x;
    if (i < NN) {
        int o = off[i] + blk[i >> 10];
        off[i] = o;
        cur[i] = o;
    }
    if (i == 0) off[NN] = blk[NB_SCAN];
}

__global__ void csr_fill(const int* __restrict__ ei) {
    int i = blockIdx.x * blockDim.x + threadIdx.x;
    if (i >= EE) return;
    int d = ei[EE + i];
    int pos = atomicAdd(&g_curA[d], 1);
    g_payA[pos] = i;
    if (i < E2) {
        int p1 = atomicAdd(&g_curH[ei[i]], 1);
        g_payH[p1] = i;
        int p2 = atomicAdd(&g_curH[ei[EE + i]], 1);
        g_payH[p2] = i;
    }
}

// ---------------- double-buffered SGEMM (f32x2) ----------------
template<int BM, int BN, int BK, int TM, int TN, bool QKV = false>
__global__ void __launch_bounds__((BM/TM)*(BN/TN), 2)
gemm_bias(const float* __restrict__ A, const float* __restrict__ W,
          const float* __restrict__ bias, float* __restrict__ C,
          int M, int N, int K) {
    constexpr int THREADS = (BM/TM)*(BN/TN);
    constexpr int A4 = BM*BK/4;
    constexpr int W4 = BK*BN/4;
    constexpr int AI = (A4 + THREADS - 1)/THREADS;
    constexpr int WI = (W4 + THREADS - 1)/THREADS;
    __shared__ float As[2][BK][BM+4];
    __shared__ float Ws[2][BK][BN];
    const int tid  = threadIdx.x;
    const int brow = blockIdx.y * BM;
    const int bcol = blockIdx.x * BN;
    const int trow = (tid / (BN/TN)) * TM;
    const int tcol = (tid % (BN/TN)) * TN;

    float4 stA[AI];
    float4 stW[WI];

    auto loadg = [&](int k0) {
        #pragma unroll
        for (int it = 0; it < AI; it++) {
            int i = tid + it*THREADS;
            if (i < A4) {
                int m = i / (BK/4), k4 = i % (BK/4);
                int gm = brow + m;
                stA[it] = (gm < M) ? *(const float4*)(A + (size_t)gm*K + k0 + k4*4)
                                   : make_float4(0.f,0.f,0.f,0.f);
            }
        }
        #pragma unroll
        for (int it = 0; it < WI; it++) {
            int i = tid + it*THREADS;
            if (i < W4) {
                int kk = i / (BN/4), n4 = i % (BN/4);
                stW[it] = *(const float4*)(W + (size_t)(k0+kk)*N + bcol + n4*4);
            }
        }
    };
    auto store_s = [&](int buf) {
        #pragma unroll
        for (int it = 0; it < AI; it++) {
            int i = tid + it*THREADS;
            if (i < A4) {
                int m = i / (BK/4), k4 = i % (BK/4);
                As[buf][k4*4+0][m] = stA[it].x;
                As[buf][k4*4+1][m] = stA[it].y;
                As[buf][k4*4+2][m] = stA[it].z;
                As[buf][k4*4+3][m] = stA[it].w;
            }
        }
        #pragma unroll
        for (int it = 0; it < WI; it++) {
            int i = tid + it*THREADS;
            if (i < W4) {
                int kk = i / (BN/4), n4 = i % (BN/4);
                *(float4*)&Ws[buf][kk][n4*4] = stW[it];
            }
        }
    };

    unsigned long long acc2[TM][TN/2];
    #pragma unroll
    for (int i = 0; i < TM; i++)
        #pragma unroll
        for (int j = 0; j < TN/2; j++) acc2[i][j] = 0ULL;

    const int nt = K / BK;
    loadg(0);
    store_s(0);
    __syncthreads();

    for (int t = 0; t < nt; t++) {
        int cur = t & 1;
        if (t + 1 < nt) loadg((t+1)*BK);
        #pragma unroll
        for (int kk = 0; kk < BK; kk++) {
            float ra[TM], rb[TN];
            #pragma unroll
            for (int i = 0; i < TM; i += 4)
                *(float4*)&ra[i] = *(const float4*)&As[cur][kk][trow + i];
            #pragma unroll
            for (int j = 0; j < TN; j += 4)
                *(float4*)&rb[j] = *(const float4*)&Ws[cur][kk][tcol + j];
            unsigned long long rbp[TN/2];
            #pragma unroll
            for (int j = 0; j < TN/2; j++) rbp[j] = pack2(rb[2*j], rb[2*j+1]);
            #pragma unroll
            for (int i = 0; i < TM; i++) {
                unsigned long long aa = pack2(ra[i], ra[i]);
                #pragma unroll
                for (int j = 0; j < TN/2; j++)
                    fma2(acc2[i][j], aa, rbp[j]);
            }
        }
        if (t + 1 < nt) {
            store_s((t+1) & 1);
            __syncthreads();
        }
    }

    #pragma unroll
    for (int i = 0; i < TM; i++) {
        int gm = brow + trow + i;
        if (gm >= M) continue;
        #pragma unroll
        for (int j = 0; j < TN; j += 4) {
            int gn = bcol + tcol + j;
            float2 p0 = unpack2(acc2[i][j/2]);
            float2 p1 = unpack2(acc2[i][j/2 + 1]);
            float4 v;
            v.x = p0.x + (bias ? bias[gn+0] : 0.f);
            v.y = p0.y + (bias ? bias[gn+1] : 0.f);
            v.z = p1.x + (bias ? bias[gn+2] : 0.f);
            v.w = p1.y + (bias ? bias[gn+3] : 0.f);
            if constexpr (QKV) {
                if (bcol == 0) {
                    *(float4*)(g_qf + (size_t)gm*HC + gn) = v;
                } else {
                    __half h[4];
                    h[0] = __float2half_rn(v.x); h[1] = __float2half_rn(v.y);
                    h[2] = __float2half_rn(v.z); h[3] = __float2half_rn(v.w);
                    *(uint2*)(g_kv + (size_t)gm*256 + (gn - 128)) = *(uint2*)h;
                }
            } else {
                *(float4*)(C + (size_t)gm*N + gn) = v;
            }
        }
    }
}

// ---------------- dual small GEMM (N=32) ----------------
__device__ __forceinline__ void gemm_body32(const float* __restrict__ A, const float* __restrict__ W,
                                            float* __restrict__ C, int K, int browblk) {
    __shared__ float As[2][16][132];
    __shared__ float Ws[2][16][32];
    const int tid  = threadIdx.x;
    const int brow = browblk * 128;
    const int trow = (tid / 8) * 4;
    const int tcol = (tid % 8) * 4;

    float4 stA[2];
    float4 stW;

    auto loadg = [&](int k0) {
        #pragma unroll
        for (int it = 0; it < 2; it++) {
            int i = tid + it*256;
            int m = i / 4, k4 = i % 4;
            int gm = brow + m;
            stA[it] = (gm < NN) ? *(const float4*)(A + (size_t)gm*K + k0 + k4*4)
                                : make_float4(0.f,0.f,0.f,0.f);
        }
        if (tid < 128) {
            int kk = tid / 8, n4 = tid % 8;
            stW = *(const float4*)(W + (size_t)(k0+kk)*32 + n4*4);
        }
    };
    auto store_s = [&](int buf) {
        #pragma unroll
        for (int it = 0; it < 2; it++) {
            int i = tid + it*256;
            int m = i / 4, k4 = i % 4;
            As[buf][k4*4+0][m] = stA[it].x;
            As[buf][k4*4+1][m] = stA[it].y;
            As[buf][k4*4+2][m] = stA[it].z;
            As[buf][k4*4+3][m] = stA[it].w;
        }
        if (tid < 128) {
            int kk = tid / 8, n4 = tid % 8;
            *(float4*)&Ws[buf][kk][n4*4] = stW;
        }
    };

    unsigned long long acc2[4][2];
    #pragma unroll
    for (int i = 0; i < 4; i++) { acc2[i][0] = 0ULL; acc2[i][1] = 0ULL; }

    const int nt = K / 16;
    loadg(0);
    store_s(0);
    __syncthreads();

    for (int t = 0; t < nt; t++) {
        int cur = t & 1;
        if (t + 1 < nt) loadg((t+1)*16);
        #pragma unroll
        for (int kk = 0; kk < 16; kk++) {
            float ra[4], rb[4];
            *(float4*)&ra[0] = *(const float4*)&As[cur][kk][trow];
            *(float4*)&rb[0] = *(const float4*)&Ws[cur][kk][tcol];
            unsigned long long rbp0 = pack2(rb[0], rb[1]);
            unsigned long long rbp1 = pack2(rb[2], rb[3]);
            #pragma unroll
            for (int i = 0; i < 4; i++) {
                unsigned long long aa = pack2(ra[i], ra[i]);
                fma2(acc2[i][0], aa, rbp0);
                fma2(acc2[i][1], aa, rbp1);
            }
        }
        if (t + 1 < nt) {
            store_s((t+1) & 1);
            __syncthreads();
        }
    }

    #pragma unroll
    for (int i = 0; i < 4; i++) {
        int gm = brow + trow + i;
        if (gm >= NN) continue;
        float2 p0 = unpack2(acc2[i][0]);
        float2 p1 = unpack2(acc2[i][1]);
        float4 v = make_float4(p0.x, p0.y, p1.x, p1.y);
        *(float4*)(C + (size_t)gm*32 + tcol) = v;
    }
}

#define NB32 ((NN + 127) / 128)
__global__ void __launch_bounds__(256, 2) gemm_dual() {
    bool second = blockIdx.y >= NB32;
    const float* A = second ? g_axh : g_ay;
    const float* W = second ? g_wh  : g_wbig;
    float*       C = second ? g_o1  : g_xgat;
    int          K = second ? 256   : AYW;
    int        blk = second ? (blockIdx.y - NB32) : blockIdx.y;
    gemm_body32(A, W, C, K, blk);
}

// ---------------- u precompute ----------------
#define GN 32
__global__ void compute_u() {
    extern __shared__ float shm[];
    float (*sW)[132] = (float (*)[132])shm;
    float (*sq)[128] = (float (*)[128])(shm + 128*132);
    int tid = threadIdx.x;
    int n0 = blockIdx.x * GN;
    for (int i = tid; i < 128*128; i += 256) {
        int o = i >> 7, f = i & 127;
        sW[o][f] = g_we2t[i];
    }
    for (int i = tid; i < GN*128; i += 256) {
        int nl = i >> 7, c = i & 127;
        int n = n0 + nl;
        sq[nl][c] = (n < NN) ? g_qf[(size_t)n*HC + c] : 0.f;
    }
    __syncthreads();
    int w = tid >> 5, lane = tid & 31;
    for (int p = w; p < GN*HH; p += 8) {
        int nl = p >> 2, h = p & 3;
        int n = n0 + nl;
        if (n >= NN) continue;
        float a0=0.f, a1=0.f, a2=0.f, a3=0.f;
        #pragma unroll
        for (int c = 0; c < 32; c++) {
            float qv = sq[nl][h*32 + c];
            const float* row = sW[h*32 + c];
            a0 = fmaf(qv, row[lane],      a0);
            a1 = fmaf(qv, row[lane + 32], a1);
            a2 = fmaf(qv, row[lane + 64], a2);
            a3 = fmaf(qv, row[lane + 96], a3);
        }
        size_t base = (size_t)n*512 + h*128;
        g_u[base + lane]      = a0;
        g_u[base + lane + 32] = a1;
        g_u[base + lane + 64] = a2;
        g_u[base + lane + 96] = a3;
    }
}

// ---------------- fused edge kernel: u+q in smem, occ 4, fp16 kv gathers ----------------
__global__ void __launch_bounds__(256, 4)
edge_fused(const int* __restrict__ ei, const float* __restrict__ ea,
           const float* __restrict__ be2, const float* __restrict__ x) {
    const unsigned FULL = 0xffffffffu;
    __shared__ float su[8][5][132];   // rows 0-3: u, row 4: q
    const int lane = threadIdx.x & 31;
    const int w = threadIdx.x >> 5;
    const int node = (blockIdx.x >> 1) * 8 + w;
    if (node >= NN) return;

    if ((blockIdx.x & 1) == 0) {
        const int g = lane >> 3, sub = lane & 7;
        const int d = node;
        const int beg = g_offA[d], end = g_offA[d+1];
        const float scale = 0.17677669529663687f;

        float4 qv0 = *(const float4*)&g_qf[(size_t)d*HC + g*32 + sub*4];
        float4 b2 = *(const float4*)&be2[g*32 + sub*4];
        float qb2 = qv0.x*b2.x + qv0.y*b2.y + qv0.z*b2.z + qv0.w*b2.w;
        #pragma unroll
        for (int j = 0; j < 4; j++) {
            float4 t4 = *(const float4*)&g_u[(size_t)d*512 + g*128 + sub*16 + j*4];
            *(float4*)&su[w][j][lane*4] = t4;
        }
        *(float4*)&su[w][4][lane*4] = qv0;
        __syncwarp();

        unsigned long long vaP0 = 0ULL, vaP1 = 0ULL;
        unsigned long long y0P0 = 0ULL, y0P1 = 0ULL;
        unsigned long long y1P0 = 0ULL, y1P1 = 0ULL;
        unsigned long long y2P0 = 0ULL, y2P1 = 0ULL;
        unsigned long long y3P0 = 0ULL, y3P1 = 0ULL;
        float s1 = 0.f, s20 = 0.f, s21 = 0.f, s22 = 0.f, s23 = 0.f;

        for (int base = beg; base < end; base += 32) {
            int m = end - base; if (m > 32) m = 32;
            int eL = 0, sL = 0;
            if (base + lane < end) {
                eL = g_payA[base + lane];
                sL = ei[eL];
            }
            int it = 0;
            for (; it + 1 < m; it += 2) {
                int e0 = __shfl_sync(FULL, eL, it),   s0  = __shfl_sync(FULL, sL, it);
                int e1 = __shfl_sync(FULL, eL, it+1), s1i = __shfl_sync(FULL, sL, it+1);
                const float* eb0 = ea + (size_t)e0*128;
                const float* eb1 = ea + (size_t)e1*128;
                const __half* kv0 = g_kv + (size_t)s0*256;
                const __half* kv1 = g_kv + (size_t)s1i*256;

                float4 qv = *(const float4*)&su[w][4][lane*4];
                uint2 kr0 = *(const uint2*)(kv0 + g*32 + sub*4);
                uint2 kr1 = *(const uint2*)(kv1 + g*32 + sub*4);
                float2 t;
                t = __half22float2(*(__half2*)&kr0.x);
                float p1a = qv.x*t.x + qv.y*t.y;
                t = __half22float2(*(__half2*)&kr0.y);
                p1a += qv.z*t.x + qv.w*t.y;
                t = __half22float2(*(__half2*)&kr1.x);
                float p1b = qv.x*t.x + qv.y*t.y;
                t = __half22float2(*(__half2*)&kr1.y);
                p1b += qv.z*t.x + qv.w*t.y;
                float p2a = qb2, p2b = qb2;
                #pragma unroll
                for (int j = 0; j < 4; j++) {
                    float4 uj = *(const float4*)&su[w][j][lane*4];
                    float4 ev0 = *(const float4*)&eb0[sub*16 + j*4];
                    float4 ev1 = *(const float4*)&eb1[sub*16 + j*4];
                    p2a += ev0.x*uj.x + ev0.y*uj.y + ev0.z*uj.z + ev0.w*uj.w;
                    p2b += ev1.x*uj.x + ev1.y*uj.y + ev1.z*uj.z + ev1.w*uj.w;
                }
                #pragma unroll
                for (int o = 1; o < 8; o <<= 1) {
                    p1a += __shfl_xor_sync(FULL, p1a, o);
                    p2a += __shfl_xor_sync(FULL, p2a, o);
                    p1b += __shfl_xor_sync(FULL, p1b, o);
                    p2b += __shfl_xor_sync(FULL, p2b, o);
                }
                float ex1a = __expf(p1a * scale), ex2a = __expf(p2a * scale);
                float ex1b = __expf(p1b * scale), ex2b = __expf(p2b * scale);
                s1 += ex1a + ex1b;
                float e20a = __shfl_sync(FULL, ex2a, 0),  e20b = __shfl_sync(FULL, ex2b, 0);
                float e21a = __shfl_sync(FULL, ex2a, 8),  e21b = __shfl_sync(FULL, ex2b, 8);
                float e22a = __shfl_sync(FULL, ex2a, 16), e22b = __shfl_sync(FULL, ex2b, 16);
                float e23a = __shfl_sync(FULL, ex2a, 24), e23b = __shfl_sync(FULL, ex2b, 24);
                s20 += e20a + e20b; s21 += e21a + e21b;
                s22 += e22a + e22b; s23 += e23a + e23b;

                float4 ey0 = *(const float4*)&eb0[lane*4];
                float4 ey1 = *(const float4*)&eb1[lane*4];
                uint2 vr0 = *(const uint2*)(kv0 + 128 + lane*4);
                uint2 vr1 = *(const uint2*)(kv1 + 128 + lane*4);
                unsigned long long ey0lo = pack2(ey0.x, ey0.y), ey0hi = pack2(ey0.z, ey0.w);
                unsigned long long ey1lo = pack2(ey1.x, ey1.y), ey1hi = pack2(ey1.z, ey1.w);
                unsigned long long x1a = pack2(ex1a, ex1a), x1b = pack2(ex1b, ex1b);
                t = __half22float2(*(__half2*)&vr0.x);
                fma2(vaP0, x1a, pack2(t.x, t.y));
                t = __half22float2(*(__half2*)&vr0.y);
                fma2(vaP1, x1a, pack2(t.x, t.y));
                t = __half22float2(*(__half2*)&vr1.x);
                fma2(vaP0, x1b, pack2(t.x, t.y));
                t = __half22float2(*(__half2*)&vr1.y);
                fma2(vaP1, x1b, pack2(t.x, t.y));
                unsigned long long c0a = pack2(e20a, e20a), c0b = pack2(e20b, e20b);
                fma2(y0P0, c0a, ey0lo); fma2(y0P0, c0b, ey1lo);
                fma2(y0P1, c0a, ey0hi); fma2(y0P1, c0b, ey1hi);
                unsigned long long c1a = pack2(e21a, e21a), c1b = pack2(e21b, e21b);
                fma2(y1P0, c1a, ey0lo); fma2(y1P0, c1b, ey1lo);
                fma2(y1P1, c1a, ey0hi); fma2(y1P1, c1b, ey1hi);
                unsigned long long c2a = pack2(e22a, e22a), c2b = pack2(e22b, e22b);
                fma2(y2P0, c2a, ey0lo); fma2(y2P0, c2b, ey1lo);
                fma2(y2P1, c2a, ey0hi); fma2(y2P1, c2b, ey1hi);
                unsigned long long c3a = pack2(e23a, e23a), c3b = pack2(e23b, e23b);
                fma2(y3P0, c3a, ey0lo); fma2(y3P0, c3b, ey1lo);
                fma2(y3P1, c3a, ey0hi); fma2(y3P1, c3b, ey1hi);
            }
            if (it < m) {
                int e0 = __shfl_sync(FULL, eL, it), s0 = __shfl_sync(FULL, sL, it);
                const float* eb0 = ea + (size_t)e0*128;
                const __half* kv0 = g_kv + (size_t)s0*256;
                float4 qv = *(const float4*)&su[w][4][lane*4];
                uint2 kr0 = *(const uint2*)(kv0 + g*32 + sub*4);
                float2 t;
                t = __half22float2(*(__half2*)&kr0.x);
                float p1a = qv.x*t.x + qv.y*t.y;
                t = __half22float2(*(__half2*)&kr0.y);
                p1a += qv.z*t.x + qv.w*t.y;
                float p2a = qb2;
                #pragma unroll
                for (int j = 0; j < 4; j++) {
                    float4 uj = *(const float4*)&su[w][j][lane*4];
                    float4 ev0 = *(const float4*)&eb0[sub*16 + j*4];
                    p2a += ev0.x*uj.x + ev0.y*uj.y + ev0.z*uj.z + ev0.w*uj.w;
                }
                #pragma unroll
                for (int o = 1; o < 8; o <<= 1) {
                    p1a += __shfl_xor_sync(FULL, p1a, o);
                    p2a += __shfl_xor_sync(FULL, p2a, o);
                }
                float ex1a = __expf(p1a * scale), ex2a = __expf(p2a * scale);
                s1 += ex1a;
                float e20a = __shfl_sync(FULL, ex2a, 0);
                float e21a = __shfl_sync(FULL, ex2a, 8);
                float e22a = __shfl_sync(FULL, ex2a, 16);
                float e23a = __shfl_sync(FULL, ex2a, 24);
                s20 += e20a; s21 += e21a; s22 += e22a; s23 += e23a;
                float4 ey0 = *(const float4*)&eb0[lane*4];
                uint2 vr0 = *(const uint2*)(kv0 + 128 + lane*4);
                unsigned long long ey0lo = pack2(ey0.x, ey0.y), ey0hi = pack2(ey0.z, ey0.w);
                unsigned long long x1a = pack2(ex1a, ex1a);
                t = __half22float2(*(__half2*)&vr0.x);
                fma2(vaP0, x1a, pack2(t.x, t.y));
                t = __half22float2(*(__half2*)&vr0.y);
                fma2(vaP1, x1a, pack2(t.x, t.y));
                unsigned long long c0a = pack2(e20a, e20a);
                fma2(y0P0, c0a, ey0lo); fma2(y0P1, c0a, ey0hi);
                unsigned long long c1a = pack2(e21a, e21a);
                fma2(y1P0, c1a, ey0lo); fma2(y1P1, c1a, ey0hi);
                unsigned long long c2a = pack2(e22a, e22a);
                fma2(y2P0, c2a, ey0lo); fma2(y2P1, c2a, ey0hi);
                unsigned long long c3a = pack2(e23a, e23a);
                fma2(y3P0, c3a, ey0lo); fma2(y3P1, c3a, ey0hi);
            }
        }

        float r1 = 1.f / (s1 + 1e-16f);
        float q0 = 1.f/(s20+1e-16f), q1 = 1.f/(s21+1e-16f);
        float q2 = 1.f/(s22+1e-16f), q3 = 1.f/(s23+1e-16f);
        float2 a, b;
        float* row = g_ay + (size_t)d*AYW;
        a = unpack2(vaP0); b = unpack2(vaP1);
        *(float4*)&row[lane*4] = make_float4(a.x*r1, a.y*r1, b.x*r1, b.y*r1);
        a = unpack2(y0P0); b = unpack2(y0P1);
        *(float4*)&row[128 + 0*128 + lane*4] = make_float4(a.x*q0, a.y*q0, b.x*q0, b.y*q0);
        a = unpack2(y1P0); b = unpack2(y1P1);
        *(float4*)&row[128 + 1*128 + lane*4] = make_float4(a.x*q1, a.y*q1, b.x*q1, b.y*q1);
        a = unpack2(y2P0); b = unpack2(y2P1);
        *(float4*)&row[128 + 2*128 + lane*4] = make_float4(a.x*q2, a.y*q2, b.x*q2, b.y*q2);
        a = unpack2(y3P0); b = unpack2(y3P1);
        *(float4*)&row[128 + 3*128 + lane*4] = make_float4(a.x*q3, a.y*q3, b.x*q3, b.y*q3);
        if (lane == 0)      row[640] = (end > beg) ? 1.f : 0.f;
        else if (lane < 16) row[640 + lane] = 0.f;
    } else {
        const int n = node;
        const int beg = g_offH[n], end = g_offH[n+1];
        float4 acc = make_float4(0.f,0.f,0.f,0.f);
        for (int base = beg; base < end; base += 32) {
            int m = end - base; if (m > 32) m = 32;
            int iL = 0;
            if (base + lane < end) iL = g_payH[base + lane];
            int it = 0;
            for (; it + 1 < m; it += 2) {
                int i0 = __shfl_sync(FULL, iL, it);
                int i1 = __shfl_sync(FULL, iL, it+1);
                float4 e0 = *(const float4*)&ea[(size_t)i0*128 + lane*4];
                float4 e1 = *(const float4*)&ea[(size_t)i1*128 + lane*4];
                acc.x += e0.x + e1.x; acc.y += e0.y + e1.y;
                acc.z += e0.z + e1.z; acc.w += e0.w + e1.w;
            }
            if (it < m) {
                int i0 = __shfl_sync(FULL, iL, it);
                float4 e0 = *(const float4*)&ea[(size_t)i0*128 + lane*4];
                acc.x += e0.x; acc.y += e0.y; acc.z += e0.z; acc.w += e0.w;
            }
        }
        int len = end - beg;
        float binv = (len > 0) ? (1.f / (float)len) : 0.f;
        acc.x *= binv; acc.y *= binv; acc.z *= binv; acc.w *= binv;
        *(float4*)&g_axh[(size_t)n*256 + lane*4] = acc;
        *(float4*)&g_axh[(size_t)n*256 + 128 + lane*4] = *(const float4*)&x[(size_t)n*128 + lane*4];
    }
}

// ---------------- merged bn_stats + hyper_out ----------------
__global__ void bn_hyper(const int* __restrict__ ei, const float* __restrict__ bh,
                         float* __restrict__ out2) {
    if (blockIdx.x < 256) {
        __shared__ float ssum[8][CC], ssq[8][CC];
        int c  = threadIdx.x & 31;
        int ry = threadIdx.x >> 5;
        float s = 0.f, q = 0.f;
        for (int r = blockIdx.x * 8 + ry; r < NN; r += 256 * 8) {
            float v = g_xgat[r*CC + c];
            s += v; q += v * v;
        }
        ssum[ry][c] = s; ssq[ry][c] = q;
        __syncthreads();
        if (ry == 0) {
            #pragma unroll
            for (int i = 1; i < 8; i++) { s += ssum[i][c]; q += ssq[i][c]; }
            atomicAdd(&g_sum[c],   (double)s);
            atomicAdd(&g_sumsq[c], (double)q);
        }
    } else {
        int idx = (blockIdx.x - 256) * 256 + threadIdx.x;
        if (idx >= E2*CC) return;
        int i = idx >> 5, c = idx & 31;
        out2[idx] = 0.5f * (g_o1[ei[i]*CC + c] + g_o1[ei[EE + i]*CC + c]) + bh[c];
    }
}

__global__ void bn_final() {
    int c = threadIdx.x;
    if (c < CC) {
        double mu  = g_sum[c] / (double)NN;
        double var = g_sumsq[c] / (double)NN - mu * mu;
        g_mu[c]   = (float)mu;
        g_rstd[c] = (float)(1.0 / sqrt(var + 1e-5));
    }
}

__global__ void bn_apply(const float* __restrict__ bn_w, const float* __restrict__ bn_b,
                         float* __restrict__ out1) {
    int i = blockIdx.x * blockDim.x + threadIdx.x;
    if (i >= NN*CC) return;
    int c = i & 31;
    float xn = bn_w[c] * (g_xgat[i] - g_mu[c]) * g_rstd[c] + bn_b[c];
    out1[i] = 0.5f * xn * (1.0f + erff(xn * 0.70710678118654752f));
}

// ---------------- launcher ----------------
extern "C" void kernel_launch(void* const* d_in, const int* in_sizes, int n_in,
                              void* d_out, int out_size) {
    const float* x    = (const float*)d_in[0];
    const float* ea   = (const float*)d_in[1];
    const float* Wq   = (const float*)d_in[2];
    const float* bq   = (const float*)d_in[3];
    const float* Wk   = (const float*)d_in[4];
    const float* bk   = (const float*)d_in[5];
    const float* Wv   = (const float*)d_in[6];
    const float* bv   = (const float*)d_in[7];
    const float* We2  = (const float*)d_in[8];
    const float* be2  = (const float*)d_in[9];
    const float* We3  = (const float*)d_in[10];
    const float* be3  = (const float*)d_in[11];
    const float* Wcon = (const float*)d_in[12];
    const float* bn_w = (const float*)d_in[13];
    const float* bn_b = (const float*)d_in[14];
    const float* Wh1  = (const float*)d_in[15];
    const float* Wh2  = (const float*)d_in[16];
    const float* bh   = (const float*)d_in[17];
    const int*   ei   = (const int*)d_in[18];

    float* out  = (float*)d_out;
    float* out1 = out;
    float* out2 = out + (size_t)NN * CC;

    float *pwqkv, *pbqkv;
    cudaGetSymbolAddress((void**)&pwqkv, g_wqkv);
    cudaGetSymbolAddress((void**)&pbqkv, g_bqkv);

    const int U_SMEM = (128*132 + GN*128) * 4;
    cudaFuncSetAttribute(compute_u, cudaFuncAttributeMaxDynamicSharedMemorySize, U_SMEM);

    setup_kernel<<<256, 256>>>(We2, Wcon, We3, be3, Wh1, Wh2, Wq, bq, Wk, bk, Wv, bv);

    // CSR build (A+H combined launches)
    csr_count<<<(EE + 255)/256, 256>>>(ei);
    scan1<<<dim3(NB_SCAN, 2), 1024>>>(0);
    scan2<<<1, 64>>>(0);
    scan3<<<dim3((NN + 255)/256, 2), 256>>>(0);
    csr_fill<<<(EE + 255)/256, 256>>>(ei);

    // fused qkv projection: q -> fp32, k/v -> fp16 packed
    gemm_bias<128,128,16,8,8,true><<<dim3(3, (NN + 127)/128), 256>>>(x, pwqkv, pbqkv, nullptr, NN, QS, DINF);

    // u precompute
    compute_u<<<(NN + GN - 1)/GN, 256, U_SMEM>>>();

    // fused attention + hyper aggregation (occ 4, fp16 kv, q+u in smem)
    edge_fused<<<2 * ((NN + 7)/8), 256>>>(ei, ea, be2, x);

    // both output projections
    gemm_dual<<<dim3(1, 2*NB32), 256>>>();

    // bn stats + hyper edge output
    bn_hyper<<<256 + (E2*CC + 255)/256, 256>>>(ei, bh, out2);
    bn_final<<<1, 32>>>();
    bn_apply<<<(NN * CC + 255) / 256, 256>>>(bn_w, bn_b, out1);
}

// round 17
// speedup vs baseline: 1.5461x; 1.0393x over previous
#include <cuda_runtime.h>
#include <cuda_fp16.h>
#include <math.h>
#include <stdint.h>

#define NN 50000
#define EE 512000
#define E2 (EE/2)
#define DINF 128
#define HC 128
#define CC 32
#define HH 4
#define AYW 656   // 128 va | 512 y | 1 ind | 15 pad
#define QS 384
#define NB_SCAN ((NN + 1023) / 1024)

// ---------------- scratch ----------------
__device__ float    g_qf[(size_t)NN*HC];       // q fp32
__device__ __half   g_kv[(size_t)NN*256];      // [k | v] fp16
__device__ float    g_wqkv[DINF*QS];
__device__ float    g_bqkv[QS];
__device__ float    g_u[(size_t)NN*HH*DINF];
__device__ float    g_we2t[DINF*HC];
__device__ float    g_ay[(size_t)NN*AYW];
__device__ float    g_axh[(size_t)NN*256];
__device__ float    g_wbig[AYW*CC];
__device__ float    g_wh[256*CC];
__device__ float    g_xgat[NN*CC];
__device__ float    g_o1[NN*CC];
__device__ double   g_sum[CC];
__device__ double   g_sumsq[CC];
__device__ float    g_mu[CC];
__device__ float    g_rstd[CC];
// CSR
__device__ int      g_cntA[NN];
__device__ int      g_cntH[NN];
__device__ int      g_offA[NN+1];
__device__ int      g_offH[NN+1];
__device__ int      g_curA[NN];
__device__ int      g_curH[NN];
__device__ int      g_payA[EE];
__device__ int      g_payH[EE];
__device__ int      g_blkA[NB_SCAN+1];
__device__ int      g_blkH[NB_SCAN+1];

// ---------------- f32x2 helpers ----------------
__device__ __forceinline__ unsigned long long pack2(float lo, float hi) {
    unsigned long long r;
    asm("mov.b64 %0, {%1, %2};" : "=l"(r) : "f"(lo), "f"(hi));
    return r;
}
__device__ __forceinline__ void fma2(unsigned long long& d, unsigned long long a, unsigned long long b) {
    asm("fma.rn.f32x2 %0, %1, %2, %0;" : "+l"(d) : "l"(a), "l"(b));
}
__device__ __forceinline__ float2 unpack2(unsigned long long v) {
    float lo, hi;
    asm("mov.b64 {%0, %1}, %2;" : "=f"(lo), "=f"(hi) : "l"(v));
    return make_float2(lo, hi);
}

// ---------------- setup ----------------
__global__ void setup_kernel(const float* __restrict__ We2,
                             const float* __restrict__ Wcon, const float* __restrict__ We3,
                             const float* __restrict__ be3,
                             const float* __restrict__ Wh1, const float* __restrict__ Wh2,
                             const float* __restrict__ Wq, const float* __restrict__ bq,
                             const float* __restrict__ Wk, const float* __restrict__ bk,
                             const float* __restrict__ Wv, const float* __restrict__ bv) {
    int tid = blockIdx.x * blockDim.x + threadIdx.x;
    int stride = gridDim.x * blockDim.x;
    for (int j = tid; j < NN; j += stride) { g_cntA[j]=0; g_cntH[j]=0; }
    if (tid < CC) { g_sum[tid]=0.0; g_sumsq[tid]=0.0; }
    for (int i = tid; i < DINF*HC; i += stride) {
        int f = i >> 7, o = i & 127;
        g_we2t[o*DINF + f] = We2[i];
    }
    for (int idx = tid; idx < AYW*CC; idx += stride) {
        int r = idx / CC, c = idx % CC;
        float v;
        if (r < 128) {
            v = Wcon[r*CC + c];
        } else if (r < 640) {
            int h = (r - 128) >> 7, f = (r - 128) & 127;
            float a = 0.f;
            #pragma unroll
            for (int c2 = 0; c2 < 32; c2++)
                a = fmaf(We3[f*HC + h*32 + c2], Wcon[(h*32 + c2)*CC + c], a);
            v = a;
        } else if (r == 640) {
            float a = 0.f;
            for (int k = 0; k < HC; k++)
                a = fmaf(be3[k], Wcon[k*CC + c], a);
            v = a;
        } else v = 0.f;
        g_wbig[r*CC + c] = v;
    }
    for (int j = tid; j < 256*CC; j += stride) {
        int r = j / CC, c = j % CC;
        g_wh[r*CC + c] = (r < 128) ? Wh1[r*CC + c] : Wh2[(r-128)*CC + c];
    }
    for (int j = tid; j < DINF*QS; j += stride) {
        int f = j / QS, n = j % QS;
        float v = (n < 128) ? Wq[f*HC + n] : (n < 256) ? Wk[f*HC + n - 128] : Wv[f*HC + n - 256];
        g_wqkv[j] = v;
    }
    if (tid < QS) {
        g_bqkv[tid] = (tid < 128) ? bq[tid] : (tid < 256) ? bk[tid-128] : bv[tid-256];
    }
}

// ---------------- CSR build ----------------
__global__ void csr_count(const int* __restrict__ ei) {
    int i = blockIdx.x * blockDim.x + threadIdx.x;
    if (i >= EE) return;
    atomicAdd(&g_cntA[ei[EE + i]], 1);
    if (i < E2) {
        atomicAdd(&g_cntH[ei[i]],      1);
        atomicAdd(&g_cntH[ei[EE + i]], 1);
    }
}

__global__ void scan1(int dummy) {
    __shared__ int sd[1024];
    const int* cnt = blockIdx.y ? g_cntH : g_cntA;
    int* off = blockIdx.y ? g_offH : g_offA;
    int* blk = blockIdx.y ? g_blkH : g_blkA;
    int tid = threadIdx.x;
    int i = blockIdx.x * 1024 + tid;
    int v = (i < NN) ? cnt[i] : 0;
    sd[tid] = v;
    __syncthreads();
    #pragma unroll
    for (int ofs = 1; ofs < 1024; ofs <<= 1) {
        int t = (tid >= ofs) ? sd[tid - ofs] : 0;
        __syncthreads();
        sd[tid] += t;
        __syncthreads();
    }
    if (i < NN) off[i] = sd[tid] - v;
    if (tid == 1023) blk[blockIdx.x] = sd[1023];
}

__global__ void scan2(int dummy) {
    int* blk = (threadIdx.x >= 32) ? g_blkH : g_blkA;
    if ((threadIdx.x & 31) == 0) {
        int run = 0;
        for (int b = 0; b < NB_SCAN; b++) { int t = blk[b]; blk[b] = run; run += t; }
        blk[NB_SCAN] = run;
    }
}

__global__ void scan3(int dummy) {
    int* off = blockIdx.y ? g_offH : g_offA;
    int* cur = blockIdx.y ? g_curH : g_curA;
    const int* blk = blockIdx.y ? g_blkH : g_blkA;
    int i = blockIdx.x * blockDim.x + threadIdx.x;
    if (i < NN) {
        int o = off[i] + blk[i >> 10];
        off[i] = o;
        cur[i] = o;
    }
    if (i == 0) off[NN] = blk[NB_SCAN];
}

__global__ void csr_fill(const int* __restrict__ ei) {
    int i = blockIdx.x * blockDim.x + threadIdx.x;
    if (i >= EE) return;
    int d = ei[EE + i];
    int pos = atomicAdd(&g_curA[d], 1);
    g_payA[pos] = i;
    if (i < E2) {
        int p1 = atomicAdd(&g_curH[ei[i]], 1);
        g_payH[p1] = i;
        int p2 = atomicAdd(&g_curH[ei[EE + i]], 1);
        g_payH[p2] = i;
    }
}

// ---------------- double-buffered SGEMM (f32x2), MB = min blocks/SM ----------------
template<int BM, int BN, int BK, int TM, int TN, bool QKV = false, int MB = 2>
__global__ void __launch_bounds__((BM/TM)*(BN/TN), MB)
gemm_bias(const float* __restrict__ A, const float* __restrict__ W,
          const float* __restrict__ bias, float* __restrict__ C,
          int M, int N, int K) {
    constexpr int THREADS = (BM/TM)*(BN/TN);
    constexpr int A4 = BM*BK/4;
    constexpr int W4 = BK*BN/4;
    constexpr int AI = (A4 + THREADS - 1)/THREADS;
    constexpr int WI = (W4 + THREADS - 1)/THREADS;
    __shared__ float As[2][BK][BM+4];
    __shared__ float Ws[2][BK][BN];
    const int tid  = threadIdx.x;
    const int brow = blockIdx.y * BM;
    const int bcol = blockIdx.x * BN;
    const int trow = (tid / (BN/TN)) * TM;
    const int tcol = (tid % (BN/TN)) * TN;

    float4 stA[AI];
    float4 stW[WI];

    auto loadg = [&](int k0) {
        #pragma unroll
        for (int it = 0; it < AI; it++) {
            int i = tid + it*THREADS;
            if (i < A4) {
                int m = i / (BK/4), k4 = i % (BK/4);
                int gm = brow + m;
                stA[it] = (gm < M) ? *(const float4*)(A + (size_t)gm*K + k0 + k4*4)
                                   : make_float4(0.f,0.f,0.f,0.f);
            }
        }
        #pragma unroll
        for (int it = 0; it < WI; it++) {
            int i = tid + it*THREADS;
            if (i < W4) {
                int kk = i / (BN/4), n4 = i % (BN/4);
                stW[it] = *(const float4*)(W + (size_t)(k0+kk)*N + bcol + n4*4);
            }
        }
    };
    auto store_s = [&](int buf) {
        #pragma unroll
        for (int it = 0; it < AI; it++) {
            int i = tid + it*THREADS;
            if (i < A4) {
                int m = i / (BK/4), k4 = i % (BK/4);
                As[buf][k4*4+0][m] = stA[it].x;
                As[buf][k4*4+1][m] = stA[it].y;
                As[buf][k4*4+2][m] = stA[it].z;
                As[buf][k4*4+3][m] = stA[it].w;
            }
        }
        #pragma unroll
        for (int it = 0; it < WI; it++) {
            int i = tid + it*THREADS;
            if (i < W4) {
                int kk = i / (BN/4), n4 = i % (BN/4);
                *(float4*)&Ws[buf][kk][n4*4] = stW[it];
            }
        }
    };

    unsigned long long acc2[TM][TN/2];
    #pragma unroll
    for (int i = 0; i < TM; i++)
        #pragma unroll
        for (int j = 0; j < TN/2; j++) acc2[i][j] = 0ULL;

    const int nt = K / BK;
    loadg(0);
    store_s(0);
    __syncthreads();

    for (int t = 0; t < nt; t++) {
        int cur = t & 1;
        if (t + 1 < nt) loadg((t+1)*BK);
        #pragma unroll
        for (int kk = 0; kk < BK; kk++) {
            float ra[TM], rb[TN];
            #pragma unroll
            for (int i = 0; i < TM; i += 4)
                *(float4*)&ra[i] = *(const float4*)&As[cur][kk][trow + i];
            #pragma unroll
            for (int j = 0; j < TN; j += 4)
                *(float4*)&rb[j] = *(const float4*)&Ws[cur][kk][tcol + j];
            unsigned long long rbp[TN/2];
            #pragma unroll
            for (int j = 0; j < TN/2; j++) rbp[j] = pack2(rb[2*j], rb[2*j+1]);
            #pragma unroll
            for (int i = 0; i < TM; i++) {
                unsigned long long aa = pack2(ra[i], ra[i]);
                #pragma unroll
                for (int j = 0; j < TN/2; j++)
                    fma2(acc2[i][j], aa, rbp[j]);
            }
        }
        if (t + 1 < nt) {
            store_s((t+1) & 1);
            __syncthreads();
        }
    }

    #pragma unroll
    for (int i = 0; i < TM; i++) {
        int gm = brow + trow + i;
        if (gm >= M) continue;
        #pragma unroll
        for (int j = 0; j < TN; j += 4) {
            int gn = bcol + tcol + j;
            float2 p0 = unpack2(acc2[i][j/2]);
            float2 p1 = unpack2(acc2[i][j/2 + 1]);
            float4 v;
            v.x = p0.x + (bias ? bias[gn+0] : 0.f);
            v.y = p0.y + (bias ? bias[gn+1] : 0.f);
            v.z = p1.x + (bias ? bias[gn+2] : 0.f);
            v.w = p1.y + (bias ? bias[gn+3] : 0.f);
            if constexpr (QKV) {
                if (bcol < 128) {
                    *(float4*)(g_qf + (size_t)gm*HC + gn) = v;
                } else {
                    __half h[4];
                    h[0] = __float2half_rn(v.x); h[1] = __float2half_rn(v.y);
                    h[2] = __float2half_rn(v.z); h[3] = __float2half_rn(v.w);
                    *(uint2*)(g_kv + (size_t)gm*256 + (gn - 128)) = *(uint2*)h;
                }
            } else {
                *(float4*)(C + (size_t)gm*N + gn) = v;
            }
        }
    }
}

// ---------------- dual small GEMM (N=32) ----------------
__device__ __forceinline__ void gemm_body32(const float* __restrict__ A, const float* __restrict__ W,
                                            float* __restrict__ C, int K, int browblk) {
    __shared__ float As[2][16][132];
    __shared__ float Ws[2][16][32];
    const int tid  = threadIdx.x;
    const int brow = browblk * 128;
    const int trow = (tid / 8) * 4;
    const int tcol = (tid % 8) * 4;

    float4 stA[2];
    float4 stW;

    auto loadg = [&](int k0) {
        #pragma unroll
        for (int it = 0; it < 2; it++) {
            int i = tid + it*256;
            int m = i / 4, k4 = i % 4;
            int gm = brow + m;
            stA[it] = (gm < NN) ? *(const float4*)(A + (size_t)gm*K + k0 + k4*4)
                                : make_float4(0.f,0.f,0.f,0.f);
        }
        if (tid < 128) {
            int kk = tid / 8, n4 = tid % 8;
            stW = *(const float4*)(W + (size_t)(k0+kk)*32 + n4*4);
        }
    };
    auto store_s = [&](int buf) {
        #pragma unroll
        for (int it = 0; it < 2; it++) {
            int i = tid + it*256;
            int m = i / 4, k4 = i % 4;
            As[buf][k4*4+0][m] = stA[it].x;
            As[buf][k4*4+1][m] = stA[it].y;
            As[buf][k4*4+2][m] = stA[it].z;
            As[buf][k4*4+3][m] = stA[it].w;
        }
        if (tid < 128) {
            int kk = tid / 8, n4 = tid % 8;
            *(float4*)&Ws[buf][kk][n4*4] = stW;
        }
    };

    unsigned long long acc2[4][2];
    #pragma unroll
    for (int i = 0; i < 4; i++) { acc2[i][0] = 0ULL; acc2[i][1] = 0ULL; }

    const int nt = K / 16;
    loadg(0);
    store_s(0);
    __syncthreads();

    for (int t = 0; t < nt; t++) {
        int cur = t & 1;
        if (t + 1 < nt) loadg((t+1)*16);
        #pragma unroll
        for (int kk = 0; kk < 16; kk++) {
            float ra[4], rb[4];
            *(float4*)&ra[0] = *(const float4*)&As[cur][kk][trow];
            *(float4*)&rb[0] = *(const float4*)&Ws[cur][kk][tcol];
            unsigned long long rbp0 = pack2(rb[0], rb[1]);
            unsigned long long rbp1 = pack2(rb[2], rb[3]);
            #pragma unroll
            for (int i = 0; i < 4; i++) {
                unsigned long long aa = pack2(ra[i], ra[i]);
                fma2(acc2[i][0], aa, rbp0);
                fma2(acc2[i][1], aa, rbp1);
            }
        }
        if (t + 1 < nt) {
            store_s((t+1) & 1);
            __syncthreads();
        }
    }

    #pragma unroll
    for (int i = 0; i < 4; i++) {
        int gm = brow + trow + i;
        if (gm >= NN) continue;
        float2 p0 = unpack2(acc2[i][0]);
        float2 p1 = unpack2(acc2[i][1]);
        float4 v = make_float4(p0.x, p0.y, p1.x, p1.y);
        *(float4*)(C + (size_t)gm*32 + tcol) = v;
    }
}

#define NB32 ((NN + 127) / 128)
__global__ void __launch_bounds__(256, 4) gemm_dual() {
    bool second = blockIdx.y >= NB32;
    const float* A = second ? g_axh : g_ay;
    const float* W = second ? g_wh  : g_wbig;
    float*       C = second ? g_o1  : g_xgat;
    int          K = second ? 256   : AYW;
    int        blk = second ? (blockIdx.y - NB32) : blockIdx.y;
    gemm_body32(A, W, C, K, blk);
}

// ---------------- u precompute ----------------
#define GN 32
__global__ void compute_u() {
    extern __shared__ float shm[];
    float (*sW)[132] = (float (*)[132])shm;
    float (*sq)[128] = (float (*)[128])(shm + 128*132);
    int tid = threadIdx.x;
    int n0 = blockIdx.x * GN;
    for (int i = tid; i < 128*128; i += 256) {
        int o = i >> 7, f = i & 127;
        sW[o][f] = g_we2t[i];
    }
    for (int i = tid; i < GN*128; i += 256) {
        int nl = i >> 7, c = i & 127;
        int n = n0 + nl;
        sq[nl][c] = (n < NN) ? g_qf[(size_t)n*HC + c] : 0.f;
    }
    __syncthreads();
    int w = tid >> 5, lane = tid & 31;
    for (int p = w; p < GN*HH; p += 8) {
        int nl = p >> 2, h = p & 3;
        int n = n0 + nl;
        if (n >= NN) continue;
        float a0=0.f, a1=0.f, a2=0.f, a3=0.f;
        #pragma unroll
        for (int c = 0; c < 32; c++) {
            float qv = sq[nl][h*32 + c];
            const float* row = sW[h*32 + c];
            a0 = fmaf(qv, row[lane],      a0);
            a1 = fmaf(qv, row[lane + 32], a1);
            a2 = fmaf(qv, row[lane + 64], a2);
            a3 = fmaf(qv, row[lane + 96], a3);
        }
        size_t base = (size_t)n*512 + h*128;
        g_u[base + lane]      = a0;
        g_u[base + lane + 32] = a1;
        g_u[base + lane + 64] = a2;
        g_u[base + lane + 96] = a3;
    }
}

// ---------------- fused edge kernel: u+q in smem, occ 4, fp16 kv gathers ----------------
__global__ void __launch_bounds__(256, 4)
edge_fused(const int* __restrict__ ei, const float* __restrict__ ea,
           const float* __restrict__ be2, const float* __restrict__ x) {
    const unsigned FULL = 0xffffffffu;
    __shared__ float su[8][5][132];   // rows 0-3: u, row 4: q
    const int lane = threadIdx.x & 31;
    const int w = threadIdx.x >> 5;
    const int node = (blockIdx.x >> 1) * 8 + w;
    if (node >= NN) return;

    if ((blockIdx.x & 1) == 0) {
        const int g = lane >> 3, sub = lane & 7;
        const int d = node;
        const int beg = g_offA[d], end = g_offA[d+1];
        const float scale = 0.17677669529663687f;

        float4 qv0 = *(const float4*)&g_qf[(size_t)d*HC + g*32 + sub*4];
        float4 b2 = *(const float4*)&be2[g*32 + sub*4];
        float qb2 = qv0.x*b2.x + qv0.y*b2.y + qv0.z*b2.z + qv0.w*b2.w;
        #pragma unroll
        for (int j = 0; j < 4; j++) {
            float4 t4 = *(const float4*)&g_u[(size_t)d*512 + g*128 + sub*16 + j*4];
            *(float4*)&su[w][j][lane*4] = t4;
        }
        *(float4*)&su[w][4][lane*4] = qv0;
        __syncwarp();

        unsigned long long vaP0 = 0ULL, vaP1 = 0ULL;
        unsigned long long y0P0 = 0ULL, y0P1 = 0ULL;
        unsigned long long y1P0 = 0ULL, y1P1 = 0ULL;
        unsigned long long y2P0 = 0ULL, y2P1 = 0ULL;
        unsigned long long y3P0 = 0ULL, y3P1 = 0ULL;
        float s1 = 0.f, s20 = 0.f, s21 = 0.f, s22 = 0.f, s23 = 0.f;

        for (int base = beg; base < end; base += 32) {
            int m = end - base; if (m > 32) m = 32;
            int eL = 0, sL = 0;
            if (base + lane < end) {
                eL = g_payA[base + lane];
                sL = ei[eL];
            }
            int it = 0;
            for (; it + 1 < m; it += 2) {
                int e0 = __shfl_sync(FULL, eL, it),   s0  = __shfl_sync(FULL, sL, it);
                int e1 = __shfl_sync(FULL, eL, it+1), s1i = __shfl_sync(FULL, sL, it+1);
                const float* eb0 = ea + (size_t)e0*128;
                const float* eb1 = ea + (size_t)e1*128;
                const __half* kv0 = g_kv + (size_t)s0*256;
                const __half* kv1 = g_kv + (size_t)s1i*256;

                float4 qv = *(const float4*)&su[w][4][lane*4];
                uint2 kr0 = *(const uint2*)(kv0 + g*32 + sub*4);
                uint2 kr1 = *(const uint2*)(kv1 + g*32 + sub*4);
                float2 t;
                t = __half22float2(*(__half2*)&kr0.x);
                float p1a = qv.x*t.x + qv.y*t.y;
                t = __half22float2(*(__half2*)&kr0.y);
                p1a += qv.z*t.x + qv.w*t.y;
                t = __half22float2(*(__half2*)&kr1.x);
                float p1b = qv.x*t.x + qv.y*t.y;
                t = __half22float2(*(__half2*)&kr1.y);
                p1b += qv.z*t.x + qv.w*t.y;
                float p2a = qb2, p2b = qb2;
                #pragma unroll
                for (int j = 0; j < 4; j++) {
                    float4 uj = *(const float4*)&su[w][j][lane*4];
                    float4 ev0 = *(const float4*)&eb0[sub*16 + j*4];
                    float4 ev1 = *(const float4*)&eb1[sub*16 + j*4];
                    p2a += ev0.x*uj.x + ev0.y*uj.y + ev0.z*uj.z + ev0.w*uj.w;
                    p2b += ev1.x*uj.x + ev1.y*uj.y + ev1.z*uj.z + ev1.w*uj.w;
                }
                #pragma unroll
                for (int o = 1; o < 8; o <<= 1) {
                    p1a += __shfl_xor_sync(FULL, p1a, o);
                    p2a += __shfl_xor_sync(FULL, p2a, o);
                    p1b += __shfl_xor_sync(FULL, p1b, o);
                    p2b += __shfl_xor_sync(FULL, p2b, o);
                }
                float ex1a = __expf(p1a * scale), ex2a = __expf(p2a * scale);
                float ex1b = __expf(p1b * scale), ex2b = __expf(p2b * scale);
                s1 += ex1a + ex1b;
                float e20a = __shfl_sync(FULL, ex2a, 0),  e20b = __shfl_sync(FULL, ex2b, 0);
                float e21a = __shfl_sync(FULL, ex2a, 8),  e21b = __shfl_sync(FULL, ex2b, 8);
                float e22a = __shfl_sync(FULL, ex2a, 16), e22b = __shfl_sync(FULL, ex2b, 16);
                float e23a = __shfl_sync(FULL, ex2a, 24), e23b = __shfl_sync(FULL, ex2b, 24);
                s20 += e20a + e20b; s21 += e21a + e21b;
                s22 += e22a + e22b; s23 += e23a + e23b;

                float4 ey0 = *(const float4*)&eb0[lane*4];
                float4 ey1 = *(const float4*)&eb1[lane*4];
                uint2 vr0 = *(const uint2*)(kv0 + 128 + lane*4);
                uint2 vr1 = *(const uint2*)(kv1 + 128 + lane*4);
                unsigned long long ey0lo = pack2(ey0.x, ey0.y), ey0hi = pack2(ey0.z, ey0.w);
                unsigned long long ey1lo = pack2(ey1.x, ey1.y), ey1hi = pack2(ey1.z, ey1.w);
                unsigned long long x1a = pack2(ex1a, ex1a), x1b = pack2(ex1b, ex1b);
                t = __half22float2(*(__half2*)&vr0.x);
                fma2(vaP0, x1a, pack2(t.x, t.y));
                t = __half22float2(*(__half2*)&vr0.y);
                fma2(vaP1, x1a, pack2(t.x, t.y));
                t = __half22float2(*(__half2*)&vr1.x);
                fma2(vaP0, x1b, pack2(t.x, t.y));
                t = __half22float2(*(__half2*)&vr1.y);
                fma2(vaP1, x1b, pack2(t.x, t.y));
                unsigned long long c0a = pack2(e20a, e20a), c0b = pack2(e20b, e20b);
                fma2(y0P0, c0a, ey0lo); fma2(y0P0, c0b, ey1lo);
                fma2(y0P1, c0a, ey0hi); fma2(y0P1, c0b, ey1hi);
                unsigned long long c1a = pack2(e21a, e21a), c1b = pack2(e21b, e21b);
                fma2(y1P0, c1a, ey0lo); fma2(y1P0, c1b, ey1lo);
                fma2(y1P1, c1a, ey0hi); fma2(y1P1, c1b, ey1hi);
                unsigned long long c2a = pack2(e22a, e22a), c2b = pack2(e22b, e22b);
                fma2(y2P0, c2a, ey0lo); fma2(y2P0, c2b, ey1lo);
                fma2(y2P1, c2a, ey0hi); fma2(y2P1, c2b, ey1hi);
                unsigned long long c3a = pack2(e23a, e23a), c3b = pack2(e23b, e23b);
                fma2(y3P0, c3a, ey0lo); fma2(y3P0, c3b, ey1lo);
                fma2(y3P1, c3a, ey0hi); fma2(y3P1, c3b, ey1hi);
            }
            if (it < m) {
                int e0 = __shfl_sync(FULL, eL, it), s0 = __shfl_sync(FULL, sL, it);
                const float* eb0 = ea + (size_t)e0*128;
                const __half* kv0 = g_kv + (size_t)s0*256;
                float4 qv = *(const float4*)&su[w][4][lane*4];
                uint2 kr0 = *(const uint2*)(kv0 + g*32 + sub*4);
                float2 t;
                t = __half22float2(*(__half2*)&kr0.x);
                float p1a = qv.x*t.x + qv.y*t.y;
                t = __half22float2(*(__half2*)&kr0.y);
                p1a += qv.z*t.x + qv.w*t.y;
                float p2a = qb2;
                #pragma unroll
                for (int j = 0; j < 4; j++) {
                    float4 uj = *(const float4*)&su[w][j][lane*4];
                    float4 ev0 = *(const float4*)&eb0[sub*16 + j*4];
                    p2a += ev0.x*uj.x + ev0.y*uj.y + ev0.z*uj.z + ev0.w*uj.w;
                }
                #pragma unroll
                for (int o = 1; o < 8; o <<= 1) {
                    p1a += __shfl_xor_sync(FULL, p1a, o);
                    p2a += __shfl_xor_sync(FULL, p2a, o);
                }
                float ex1a = __expf(p1a * scale), ex2a = __expf(p2a * scale);
                s1 += ex1a;
                float e20a = __shfl_sync(FULL, ex2a, 0);
                float e21a = __shfl_sync(FULL, ex2a, 8);
                float e22a = __shfl_sync(FULL, ex2a, 16);
                float e23a = __shfl_sync(FULL, ex2a, 24);
                s20 += e20a; s21 += e21a; s22 += e22a; s23 += e23a;
                float4 ey0 = *(const float4*)&eb0[lane*4];
                uint2 vr0 = *(const uint2*)(kv0 + 128 + lane*4);
                unsigned long long ey0lo = pack2(ey0.x, ey0.y), ey0hi = pack2(ey0.z, ey0.w);
                unsigned long long x1a = pack2(ex1a, ex1a);
                t = __half22float2(*(__half2*)&vr0.x);
                fma2(vaP0, x1a, pack2(t.x, t.y));
                t = __half22float2(*(__half2*)&vr0.y);
                fma2(vaP1, x1a, pack2(t.x, t.y));
                unsigned long long c0a = pack2(e20a, e20a);
                fma2(y0P0, c0a, ey0lo); fma2(y0P1, c0a, ey0hi);
                unsigned long long c1a = pack2(e21a, e21a);
                fma2(y1P0, c1a, ey0lo); fma2(y1P1, c1a, ey0hi);
                unsigned long long c2a = pack2(e22a, e22a);
                fma2(y2P0, c2a, ey0lo); fma2(y2P1, c2a, ey0hi);
                unsigned long long c3a = pack2(e23a, e23a);
                fma2(y3P0, c3a, ey0lo); fma2(y3P1, c3a, ey0hi);
            }
        }

        float r1 = 1.f / (s1 + 1e-16f);
        float q0 = 1.f/(s20+1e-16f), q1 = 1.f/(s21+1e-16f);
        float q2 = 1.f/(s22+1e-16f), q3 = 1.f/(s23+1e-16f);
        float2 a, b;
        float* row = g_ay + (size_t)d*AYW;
        a = unpack2(vaP0); b = unpack2(vaP1);
        *(float4*)&row[lane*4] = make_float4(a.x*r1, a.y*r1, b.x*r1, b.y*r1);
        a = unpack2(y0P0); b = unpack2(y0P1);
        *(float4*)&row[128 + 0*128 + lane*4] = make_float4(a.x*q0, a.y*q0, b.x*q0, b.y*q0);
        a = unpack2(y1P0); b = unpack2(y1P1);
        *(float4*)&row[128 + 1*128 + lane*4] = make_float4(a.x*q1, a.y*q1, b.x*q1, b.y*q1);
        a = unpack2(y2P0); b = unpack2(y2P1);
        *(float4*)&row[128 + 2*128 + lane*4] = make_float4(a.x*q2, a.y*q2, b.x*q2, b.y*q2);
        a = unpack2(y3P0); b = unpack2(y3P1);
        *(float4*)&row[128 + 3*128 + lane*4] = make_float4(a.x*q3, a.y*q3, b.x*q3, b.y*q3);
        if (lane == 0)      row[640] = (end > beg) ? 1.f : 0.f;
        else if (lane < 16) row[640 + lane] = 0.f;
    } else {
        const int n = node;
        const int beg = g_offH[n], end = g_offH[n+1];
        float4 acc = make_float4(0.f,0.f,0.f,0.f);
        for (int base = beg; base < end; base += 32) {
            int m = end - base; if (m > 32) m = 32;
            int iL = 0;
            if (base + lane < end) iL = g_payH[base + lane];
            int it = 0;
            for (; it + 1 < m; it += 2) {
                int i0 = __shfl_sync(FULL, iL, it);
                int i1 = __shfl_sync(FULL, iL, it+1);
                float4 e0 = *(const float4*)&ea[(size_t)i0*128 + lane*4];
                float4 e1 = *(const float4*)&ea[(size_t)i1*128 + lane*4];
                acc.x += e0.x + e1.x; acc.y += e0.y + e1.y;
                acc.z += e0.z + e1.z; acc.w += e0.w + e1.w;
            }
            if (it < m) {
                int i0 = __shfl_sync(FULL, iL, it);
                float4 e0 = *(const float4*)&ea[(size_t)i0*128 + lane*4];
                acc.x += e0.x; acc.y += e0.y; acc.z += e0.z; acc.w += e0.w;
            }
        }
        int len = end - beg;
        float binv = (len > 0) ? (1.f / (float)len) : 0.f;
        acc.x *= binv; acc.y *= binv; acc.z *= binv; acc.w *= binv;
        *(float4*)&g_axh[(size_t)n*256 + lane*4] = acc;
        *(float4*)&g_axh[(size_t)n*256 + 128 + lane*4] = *(const float4*)&x[(size_t)n*128 + lane*4];
    }
}

// ---------------- merged bn_stats + hyper_out ----------------
__global__ void bn_hyper(const int* __restrict__ ei, const float* __restrict__ bh,
                         float* __restrict__ out2) {
    if (blockIdx.x < 256) {
        __shared__ float ssum[8][CC], ssq[8][CC];
        int c  = threadIdx.x & 31;
        int ry = threadIdx.x >> 5;
        float s = 0.f, q = 0.f;
        for (int r = blockIdx.x * 8 + ry; r < NN; r += 256 * 8) {
            float v = g_xgat[r*CC + c];
            s += v; q += v * v;
        }
        ssum[ry][c] = s; ssq[ry][c] = q;
        __syncthreads();
        if (ry == 0) {
            #pragma unroll
            for (int i = 1; i < 8; i++) { s += ssum[i][c]; q += ssq[i][c]; }
            atomicAdd(&g_sum[c],   (double)s);
            atomicAdd(&g_sumsq[c], (double)q);
        }
    } else {
        int idx = (blockIdx.x - 256) * 256 + threadIdx.x;
        if (idx >= E2*CC) return;
        int i = idx >> 5, c = idx & 31;
        out2[idx] = 0.5f * (g_o1[ei[i]*CC + c] + g_o1[ei[EE + i]*CC + c]) + bh[c];
    }
}

__global__ void bn_final() {
    int c = threadIdx.x;
    if (c < CC) {
        double mu  = g_sum[c] / (double)NN;
        double var = g_sumsq[c] / (double)NN - mu * mu;
        g_mu[c]   = (float)mu;
        g_rstd[c] = (float)(1.0 / sqrt(var + 1e-5));
    }
}

__global__ void bn_apply(const float* __restrict__ bn_w, const float* __restrict__ bn_b,
                         float* __restrict__ out1) {
    int i = blockIdx.x * blockDim.x + threadIdx.x;
    if (i >= NN*CC) return;
    int c = i & 31;
    float xn = bn_w[c] * (g_xgat[i] - g_mu[c]) * g_rstd[c] + bn_b[c];
    out1[i] = 0.5f * xn * (1.0f + erff(xn * 0.70710678118654752f));
}

// ---------------- launcher ----------------
extern "C" void kernel_launch(void* const* d_in, const int* in_sizes, int n_in,
                              void* d_out, int out_size) {
    const float* x    = (const float*)d_in[0];
    const float* ea   = (const float*)d_in[1];
    const float* Wq   = (const float*)d_in[2];
    const float* bq   = (const float*)d_in[3];
    const float* Wk   = (const float*)d_in[4];
    const float* bk   = (const float*)d_in[5];
    const float* Wv   = (const float*)d_in[6];
    const float* bv   = (const float*)d_in[7];
    const float* We2  = (const float*)d_in[8];
    const float* be2  = (const float*)d_in[9];
    const float* We3  = (const float*)d_in[10];
    const float* be3  = (const float*)d_in[11];
    const float* Wcon = (const float*)d_in[12];
    const float* bn_w = (const float*)d_in[13];
    const float* bn_b = (const float*)d_in[14];
    const float* Wh1  = (const float*)d_in[15];
    const float* Wh2  = (const float*)d_in[16];
    const float* bh   = (const float*)d_in[17];
    const int*   ei   = (const int*)d_in[18];

    float* out  = (float*)d_out;
    float* out1 = out;
    float* out2 = out + (size_t)NN * CC;

    float *pwqkv, *pbqkv;
    cudaGetSymbolAddress((void**)&pwqkv, g_wqkv);
    cudaGetSymbolAddress((void**)&pbqkv, g_bqkv);

    const int U_SMEM = (128*132 + GN*128) * 4;
    cudaFuncSetAttribute(compute_u, cudaFuncAttributeMaxDynamicSharedMemorySize, U_SMEM);

    setup_kernel<<<256, 256>>>(We2, Wcon, We3, be3, Wh1, Wh2, Wq, bq, Wk, bk, Wv, bv);

    // CSR build (A+H combined launches)
    csr_count<<<(EE + 255)/256, 256>>>(ei);
    scan1<<<dim3(NB_SCAN, 2), 1024>>>(0);
    scan2<<<1, 64>>>(0);
    scan3<<<dim3((NN + 255)/256, 2), 256>>>(0);
    csr_fill<<<(EE + 255)/256, 256>>>(ei);

    // fused qkv projection: BN=64 tile, occ 3
    gemm_bias<128,64,16,8,4,true,3><<<dim3(6, (NN + 127)/128), 256>>>(x, pwqkv, pbqkv, nullptr, NN, QS, DINF);

    // u precompute
    compute_u<<<(NN + GN - 1)/GN, 256, U_SMEM>>>();

    // fused attention + hyper aggregation (occ 4, fp16 kv, q+u in smem)
    edge_fused<<<2 * ((NN + 7)/8), 256>>>(ei, ea, be2, x);

    // both output projections (occ 4)
    gemm_dual<<<dim3(1, 2*NB32), 256>>>();

    // bn stats + hyper edge output
    bn_hyper<<<256 + (E2*CC + 255)/256, 256>>>(ei, bh, out2);
    bn_final<<<1, 32>>>();
    bn_apply<<<(NN * CC + 255) / 256, 256>>>(bn_w, bn_b, out1);
}